// round 11
// baseline (speedup 1.0000x reference)
#include <cuda_runtime.h>
#include <cuda_bf16.h>
#include <cstdint>

#define BB 4
#define SS 2048
#define FF 1024
#define DKK 1024

// ---------------- scratch (device globals; no allocs allowed) ----------------
__device__ __nv_bfloat16 g_xhi[BB*SS*FF],  g_xlo[BB*SS*FF];
__device__ __nv_bfloat16 g_Wqhi[DKK*FF],   g_Wqlo[DKK*FF];
__device__ __nv_bfloat16 g_Wkhi[DKK*FF],   g_Wklo[DKK*FF];
__device__ __nv_bfloat16 g_Wvhi[DKK*FF],   g_Wvlo[DKK*FF];
__device__ __nv_bfloat16 g_Wohi[FF*DKK],   g_Wolo[FF*DKK];
__device__ __nv_bfloat16 g_qhi[BB*SS*DKK], g_qlo[BB*SS*DKK];
__device__ __nv_bfloat16 g_khi[BB*SS*DKK], g_klo[BB*SS*DKK];
__device__ __nv_bfloat16 g_vhi[BB*SS*DKK], g_vlo[BB*SS*DKK];
__device__ __nv_bfloat16 g_vThi[BB*DKK*SS], g_vTlo[BB*DKK*SS];
__device__ float         g_psum[(size_t)BB*16*SS];   // per-tile column partial sums
__device__ float         g_rcpd[BB*SS];
__device__ __nv_bfloat16 g_Ehi[(size_t)BB*SS*SS], g_Elo[(size_t)BB*SS*SS];
__device__ __nv_bfloat16 g_chi[BB*SS*DKK], g_clo[BB*SS*DKK];

// ---------------- PTX helpers (arch-portable: sm_80+ features only) ----------
__device__ __forceinline__ uint32_t smem_to_u32(const void* p) {
    uint32_t a;
    asm("{ .reg .u64 t; cvta.to.shared.u64 t, %1; cvt.u32.u64 %0, t; }" : "=r"(a) : "l"(p));
    return a;
}
__device__ __forceinline__ void cp16(uint32_t dst, const void* src) {
    asm volatile("cp.async.cg.shared.global [%0], [%1], 16;" :: "r"(dst), "l"(src));
}
#define CP_COMMIT() asm volatile("cp.async.commit_group;" ::: "memory")
template <int N> __device__ __forceinline__ void cp_wait() {
    asm volatile("cp.async.wait_group %0;" :: "n"(N) : "memory");
}
__device__ __forceinline__ void ldmx4(uint32_t* r, uint32_t addr) {
    asm volatile("ldmatrix.sync.aligned.m8n8.x4.shared.b16 {%0,%1,%2,%3}, [%4];"
        : "=r"(r[0]), "=r"(r[1]), "=r"(r[2]), "=r"(r[3]) : "r"(addr));
}
__device__ __forceinline__ void mma16816(float* c, const uint32_t* a, const uint32_t* b) {
    asm volatile(
        "mma.sync.aligned.m16n8k16.row.col.f32.bf16.bf16.f32 "
        "{%0,%1,%2,%3}, {%4,%5,%6,%7}, {%8,%9}, {%0,%1,%2,%3};"
        : "+f"(c[0]), "+f"(c[1]), "+f"(c[2]), "+f"(c[3])
        : "r"(a[0]), "r"(a[1]), "r"(a[2]), "r"(a[3]), "r"(b[0]), "r"(b[1]));
}

// smem geometry: packed planes. Per stage:
//   A plane: 128 rows x [hi 64B | lo 64B] @ stride 144  (18432 B)
//   B plane: same                                        (18432 B)
// seg index (9i+j) mod 8 -> all eight 16B banks -> conflict-free ldmatrix.
#define BK     32
#define STRB   144
#define PA     0
#define PB     18432
#define STAGE  36864
#define STAGES 3
#define SMEM_TOTAL (STAGES * STAGE)   // 110592 B -> 2 CTAs/SM (221184 <= 228K)

#define NTHREADS 256

// ---------------------------------------------------------------------------
// Core NT GEMM via mma.sync, bf16 hi/lo split (3 MMA terms), term-major issue.
// 8 warps (4x2), warp tile 32x64, CTA tile 128x128, BK=32, 3-stage pipeline,
// one __syncthreads per chunk, always >=1 full chunk of load lookahead.
// If psum != nullptr: epilogue computes E=exp(alpha*acc), writes E hi/lo to
// Chi/Clo, and deterministic per-tile column sums to psum[0..127].
// ---------------------------------------------------------------------------
__device__ __forceinline__ void gemm_core(
    const __nv_bfloat16* __restrict__ A0, const __nv_bfloat16* __restrict__ A1,
    const __nv_bfloat16* __restrict__ B0, const __nv_bfloat16* __restrict__ B1,
    float* __restrict__ Cf, __nv_bfloat16* __restrict__ Chi, __nv_bfloat16* __restrict__ Clo,
    const float* __restrict__ bias, float* __restrict__ psum,
    int K, int lda, int ldb, int ldc,
    size_t bm, size_t bn, float alpha)
{
    extern __shared__ char smem[];
    uint32_t sbase = smem_to_u32(smem);
    int tid = threadIdx.x;
    int lane = tid & 31;
    int warp = tid >> 5;
    int m0w = (warp >> 1) * 32;     // warp tile 32(m) x 64(n), 4x2 warps
    int n0w = (warp & 1) * 64;

    float acc[2][8][4];
#pragma unroll
    for (int i = 0; i < 2; i++)
#pragma unroll
        for (int j = 0; j < 8; j++)
#pragma unroll
            for (int t = 0; t < 4; t++) acc[i][j][t] = 0.0f;

    int nch = K >> 5;   // K/32 chunks

    // packed prefetch: 2048 cp16 per chunk (A hi+lo, B hi+lo), 8 per thread
    auto prefetch = [&](int c) {
        int k0 = c << 5;
        uint32_t sb = sbase + (uint32_t)(c % STAGES) * STAGE;
#pragma unroll
        for (int it = 0; it < 4; it++) {
            int id = tid + it * NTHREADS;     // 0..1023 (within a plane's 1024 ops)
            int row = id >> 3;                // 0..127
            int seg = id & 7;                 // 0..7; seg<4 = hi, seg>=4 = lo
            uint32_t doff = (uint32_t)(row * STRB + seg * 16);
            int kc = (seg & 3) * 8;
            size_t ea = (size_t)row * lda + k0 + kc;
            size_t eb = (size_t)row * ldb + k0 + kc;
            cp16(sb + PA + doff, (seg < 4 ? A0 : A1) + ea);
            cp16(sb + PB + doff, (seg < 4 ? B0 : B1) + eb);
        }
    };

    int aRow = m0w + (lane & 15);
    uint32_t aColB = (uint32_t)((lane >> 4) * 16);
    int bRow = n0w + ((lane >> 4) << 3) + (lane & 7);
    uint32_t bColB = (uint32_t)(((lane >> 3) & 1) * 16);

    prefetch(0); CP_COMMIT();
    if (nch > 1) { prefetch(1); CP_COMMIT(); }
    else CP_COMMIT();

    for (int c = 0; c < nch; c++) {
        cp_wait<1>();      // chunk c landed; chunk c+1 may still be in flight
        __syncthreads();   // visibility of chunk c + WAR guard for (c+2)%3
        if (c + 2 < nch) prefetch(c + 2);
        CP_COMMIT();       // unconditional: keeps one group per iteration

        uint32_t sb = sbase + (uint32_t)(c % STAGES) * STAGE;
#pragma unroll
        for (int ks = 0; ks < 2; ks++) {
            uint32_t kB = (uint32_t)(ks * 32);
            uint32_t a_hi[2][4], a_lo[2][4];
#pragma unroll
            for (int mf = 0; mf < 2; mf++) {
                uint32_t off = (uint32_t)((aRow + mf * 16) * STRB) + kB + aColB;
                ldmx4(a_hi[mf], sb + PA + off);
                ldmx4(a_lo[mf], sb + PA + off + 64);
            }
            uint32_t b_hi[16], b_lo[16];
#pragma unroll
            for (int ng = 0; ng < 4; ng++) {
                uint32_t off = (uint32_t)((bRow + ng * 16) * STRB) + kB + bColB;
                ldmx4(&b_hi[ng * 4], sb + PB + off);
                ldmx4(&b_lo[ng * 4], sb + PB + off + 64);
            }
            // term-major sweeps: 16 independent accumulators per sweep
#pragma unroll
            for (int mf = 0; mf < 2; mf++)
#pragma unroll
                for (int nf = 0; nf < 8; nf++)
                    mma16816(acc[mf][nf], a_hi[mf], &b_hi[nf * 2]);
#pragma unroll
            for (int mf = 0; mf < 2; mf++)
#pragma unroll
                for (int nf = 0; nf < 8; nf++)
                    mma16816(acc[mf][nf], a_hi[mf], &b_lo[nf * 2]);
#pragma unroll
            for (int mf = 0; mf < 2; mf++)
#pragma unroll
                for (int nf = 0; nf < 8; nf++)
                    mma16816(acc[mf][nf], a_lo[mf], &b_hi[nf * 2]);
        }
    }

    int gidr = lane >> 2;
    int tidq = lane & 3;

    if (psum) {
        // exp epilogue: E = exp(alpha*acc), write hi/lo, deterministic col sums
        float cs[8][2];
#pragma unroll
        for (int nf = 0; nf < 8; nf++) { cs[nf][0] = 0.0f; cs[nf][1] = 0.0f; }
#pragma unroll
        for (int mf = 0; mf < 2; mf++) {
#pragma unroll
            for (int nf = 0; nf < 8; nf++) {
                size_t r0 = bm + m0w + mf * 16 + gidr;
                size_t r1 = r0 + 8;
                size_t col = bn + n0w + nf * 8 + tidq * 2;
                float e00 = __expf(acc[mf][nf][0] * alpha);
                float e01 = __expf(acc[mf][nf][1] * alpha);
                float e10 = __expf(acc[mf][nf][2] * alpha);
                float e11 = __expf(acc[mf][nf][3] * alpha);
                cs[nf][0] += e00 + e10;
                cs[nf][1] += e01 + e11;
                __nv_bfloat162 h0 = __floats2bfloat162_rn(e00, e01);
                __nv_bfloat162 h1 = __floats2bfloat162_rn(e10, e11);
                __nv_bfloat162 l0 = __floats2bfloat162_rn(
                    e00 - __bfloat162float(__low2bfloat16(h0)),
                    e01 - __bfloat162float(__high2bfloat16(h0)));
                __nv_bfloat162 l1 = __floats2bfloat162_rn(
                    e10 - __bfloat162float(__low2bfloat16(h1)),
                    e11 - __bfloat162float(__high2bfloat16(h1)));
                *(__nv_bfloat162*)(Chi + r0 * ldc + col) = h0;
                *(__nv_bfloat162*)(Chi + r1 * ldc + col) = h1;
                *(__nv_bfloat162*)(Clo + r0 * ldc + col) = l0;
                *(__nv_bfloat162*)(Clo + r1 * ldc + col) = l1;
            }
        }
        // reduce over the 8 row-group lanes (lane bits [2:5))
#pragma unroll
        for (int nf = 0; nf < 8; nf++)
#pragma unroll
            for (int t = 0; t < 2; t++) {
                float v = cs[nf][t];
                v += __shfl_xor_sync(0xffffffff, v, 4);
                v += __shfl_xor_sync(0xffffffff, v, 8);
                v += __shfl_xor_sync(0xffffffff, v, 16);
                cs[nf][t] = v;
            }
        float* sred = (float*)smem;   // reuse pipeline smem (512 floats)
        __syncthreads();              // all warps done with MMA smem reads
        if (gidr == 0) {
#pragma unroll
            for (int nf = 0; nf < 8; nf++) {
                sred[(warp >> 1) * 128 + n0w + nf * 8 + tidq * 2 + 0] = cs[nf][0];
                sred[(warp >> 1) * 128 + n0w + nf * 8 + tidq * 2 + 1] = cs[nf][1];
            }
        }
        __syncthreads();
        if (tid < 128)
            psum[tid] = sred[tid] + sred[128 + tid] + sred[256 + tid] + sred[384 + tid];
        return;
    }

    // standard epilogue
#pragma unroll
    for (int mf = 0; mf < 2; mf++) {
#pragma unroll
        for (int nf = 0; nf < 8; nf++) {
            size_t r0 = bm + m0w + mf * 16 + gidr;
            size_t r1 = r0 + 8;
            size_t col = bn + n0w + nf * 8 + tidq * 2;
            float b0 = bias ? bias[col] : 0.0f;
            float b1 = bias ? bias[col + 1] : 0.0f;
            float c00 = acc[mf][nf][0] * alpha + b0;
            float c01 = acc[mf][nf][1] * alpha + b1;
            float c10 = acc[mf][nf][2] * alpha + b0;
            float c11 = acc[mf][nf][3] * alpha + b1;
            if (Cf) {
                *(float2*)(Cf + r0 * ldc + col) = make_float2(c00, c01);
                *(float2*)(Cf + r1 * ldc + col) = make_float2(c10, c11);
            }
            if (Chi) {
                __nv_bfloat162 h0 = __floats2bfloat162_rn(c00, c01);
                __nv_bfloat162 h1 = __floats2bfloat162_rn(c10, c11);
                __nv_bfloat162 l0 = __floats2bfloat162_rn(
                    c00 - __bfloat162float(__low2bfloat16(h0)),
                    c01 - __bfloat162float(__high2bfloat16(h0)));
                __nv_bfloat162 l1 = __floats2bfloat162_rn(
                    c10 - __bfloat162float(__low2bfloat16(h1)),
                    c11 - __bfloat162float(__high2bfloat16(h1)));
                *(__nv_bfloat162*)(Chi + r0 * ldc + col) = h0;
                *(__nv_bfloat162*)(Chi + r1 * ldc + col) = h1;
                *(__nv_bfloat162*)(Clo + r0 * ldc + col) = l0;
                *(__nv_bfloat162*)(Clo + r1 * ldc + col) = l1;
            }
        }
    }
}

// Generic batched NT GEMM (batch via blockIdx.z).
// psum_all non-null -> exp epilogue; per-tile offset computed here.
__global__ __launch_bounds__(NTHREADS, 2) void gemm_tc(
    const __nv_bfloat16* __restrict__ Ahi, const __nv_bfloat16* __restrict__ Alo,
    const __nv_bfloat16* __restrict__ Bhi, const __nv_bfloat16* __restrict__ Blo,
    float* __restrict__ Cf, __nv_bfloat16* __restrict__ Chi, __nv_bfloat16* __restrict__ Clo,
    const float* __restrict__ bias, float* __restrict__ psum_all,
    int K, int lda, int ldb, int ldc,
    long long sA, long long sB, long long sC, float alpha)
{
    int bz = blockIdx.z;
    size_t bm = (size_t)blockIdx.y * 128;
    size_t bn = (size_t)blockIdx.x * 128;
    float* ps = psum_all
        ? psum_all + ((size_t)bz * gridDim.y + blockIdx.y) * SS + bn
        : nullptr;
    gemm_core(Ahi + (size_t)bz * sA + bm * lda, Alo + (size_t)bz * sA + bm * lda,
              Bhi + (size_t)bz * sB + bn * ldb, Blo + (size_t)bz * sB + bn * ldb,
              Cf ? Cf + (size_t)bz * sC : nullptr,
              Chi ? Chi + (size_t)bz * sC : nullptr,
              Clo ? Clo + (size_t)bz * sC : nullptr,
              bias, ps, K, lda, ldb, ldc, bm, bn, alpha);
}

// Fused QKV: blockIdx.z in 0..2 selects {Wq,Wk,Wv} and output buffers.
struct QKVP {
    const __nv_bfloat16* Bh[3];
    const __nv_bfloat16* Bl[3];
    const float* bias[3];
    __nv_bfloat16* Oh[3];
    __nv_bfloat16* Ol[3];
};
__global__ __launch_bounds__(NTHREADS, 2) void gemm_qkv(
    const __nv_bfloat16* __restrict__ Ahi, const __nv_bfloat16* __restrict__ Alo,
    QKVP p, int K, int lda, int ldb, int ldc)
{
    int z = blockIdx.z;
    size_t bm = (size_t)blockIdx.y * 128;
    size_t bn = (size_t)blockIdx.x * 128;
    gemm_core(Ahi + bm * lda, Alo + bm * lda,
              p.Bh[z] + bn * ldb, p.Bl[z] + bn * ldb,
              nullptr, p.Oh[z], p.Ol[z], p.bias[z], nullptr,
              K, lda, ldb, ldc, bm, bn, 1.0f);
}

// ---------------------------------------------------------------------------
// fp32 -> bf16 hi/lo split conversion (single tensor)
// ---------------------------------------------------------------------------
__global__ __launch_bounds__(256) void conv_split(
    const float* __restrict__ in, __nv_bfloat16* __restrict__ hi,
    __nv_bfloat16* __restrict__ lo, long long n4)
{
    long long i = (long long)blockIdx.x * blockDim.x + threadIdx.x;
    if (i >= n4) return;
    float4 v = ((const float4*)in)[i];
    __nv_bfloat162 h0 = __floats2bfloat162_rn(v.x, v.y);
    __nv_bfloat162 h1 = __floats2bfloat162_rn(v.z, v.w);
    float r0 = v.x - __bfloat162float(__low2bfloat16(h0));
    float r1 = v.y - __bfloat162float(__high2bfloat16(h0));
    float r2 = v.z - __bfloat162float(__low2bfloat16(h1));
    float r3 = v.w - __bfloat162float(__high2bfloat16(h1));
    ((__nv_bfloat162*)hi)[2 * i] = h0;
    ((__nv_bfloat162*)hi)[2 * i + 1] = h1;
    ((__nv_bfloat162*)lo)[2 * i] = __floats2bfloat162_rn(r0, r1);
    ((__nv_bfloat162*)lo)[2 * i + 1] = __floats2bfloat162_rn(r2, r3);
}

// Merged conversion for the 4 weight matrices (blockIdx.y selects tensor)
struct WconvP {
    const float* in[4];
    __nv_bfloat16* hi[4];
    __nv_bfloat16* lo[4];
};
__global__ __launch_bounds__(256) void conv_split4(WconvP p, long long n4)
{
    int w = blockIdx.y;
    long long i = (long long)blockIdx.x * blockDim.x + threadIdx.x;
    if (i >= n4) return;
    float4 v = ((const float4*)p.in[w])[i];
    __nv_bfloat162 h0 = __floats2bfloat162_rn(v.x, v.y);
    __nv_bfloat162 h1 = __floats2bfloat162_rn(v.z, v.w);
    float r0 = v.x - __bfloat162float(__low2bfloat16(h0));
    float r1 = v.y - __bfloat162float(__high2bfloat16(h0));
    float r2 = v.z - __bfloat162float(__low2bfloat16(h1));
    float r3 = v.w - __bfloat162float(__high2bfloat16(h1));
    ((__nv_bfloat162*)p.hi[w])[2 * i] = h0;
    ((__nv_bfloat162*)p.hi[w])[2 * i + 1] = h1;
    ((__nv_bfloat162*)p.lo[w])[2 * i] = __floats2bfloat162_rn(r0, r1);
    ((__nv_bfloat162*)p.lo[w])[2 * i + 1] = __floats2bfloat162_rn(r2, r3);
}

// ---------------------------------------------------------------------------
// rcpd[b][col] = 1 / sum over 16 tile partials
// ---------------------------------------------------------------------------
__global__ __launch_bounds__(256) void reduce_rcpd(
    const float* __restrict__ psum, float* __restrict__ rcpd)
{
    int i = blockIdx.x * blockDim.x + threadIdx.x;   // 0..BB*SS-1
    int b = i >> 11;
    int col = i & (SS - 1);
    const float* p = psum + (size_t)b * 16 * SS + col;
    float s = 0.0f;
#pragma unroll
    for (int t = 0; t < 16; t++) s += p[(size_t)t * SS];
    rcpd[i] = 1.0f / s;
}

// ---------------------------------------------------------------------------
// bf16 transpose with per-row scale: vT[d][k] = (vhi+vlo)[k][d] * rcp[k],
// re-split into hi/lo planes. Batched.
// ---------------------------------------------------------------------------
__global__ __launch_bounds__(256) void transpose_scale(
    const __nv_bfloat16* __restrict__ ihi, const __nv_bfloat16* __restrict__ ilo,
    const float* __restrict__ rcpd,
    __nv_bfloat16* __restrict__ ohi, __nv_bfloat16* __restrict__ olo,
    int rows, int cols)
{
    __shared__ __nv_bfloat16 t0[32][33], t1[32][33];
    int z = blockIdx.z;
    size_t ioff = (size_t)z * rows * cols;
    int c0 = blockIdx.x * 32, r0 = blockIdx.y * 32;
    int tx = threadIdx.x, ty = threadIdx.y;

#pragma unroll
    for (int j = 0; j < 32; j += 8) {
        int r = r0 + ty + j;
        float rcp = rcpd[(size_t)z * rows + r];
        size_t idx = ioff + (size_t)r * cols + c0 + tx;
        float v = (__bfloat162float(ihi[idx]) + __bfloat162float(ilo[idx])) * rcp;
        __nv_bfloat16 h = __float2bfloat16(v);
        t0[ty + j][tx] = h;
        t1[ty + j][tx] = __float2bfloat16(v - __bfloat162float(h));
    }
    __syncthreads();
#pragma unroll
    for (int j = 0; j < 32; j += 8) {
        size_t odx = ioff + (size_t)(c0 + ty + j) * rows + r0 + tx;
        ohi[odx] = t0[tx][ty + j];
        olo[odx] = t1[tx][ty + j];
    }
}

// ---------------------------------------------------------------------------
extern "C" void kernel_launch(void* const* d_in, const int* in_sizes, int n_in,
                              void* d_out, int out_size)
{
    const float* x  = (const float*)d_in[0];
    const float* Wq = (const float*)d_in[1];
    const float* bq = (const float*)d_in[2];
    const float* Wk = (const float*)d_in[3];
    const float* bk = (const float*)d_in[4];
    const float* Wv = (const float*)d_in[5];
    const float* bv = (const float*)d_in[6];
    const float* Wo = (const float*)d_in[7];
    const float* bo = (const float*)d_in[8];

    __nv_bfloat16 *xhi, *xlo, *Wqhi, *Wqlo, *Wkhi, *Wklo, *Wvhi, *Wvlo, *Wohi, *Wolo;
    __nv_bfloat16 *qhi, *qlo, *khi, *klo, *vhi, *vlo, *vThi, *vTlo, *Ehi, *Elo, *chi, *clo;
    float *psum, *rcpd;
    cudaGetSymbolAddress((void**)&xhi, g_xhi);   cudaGetSymbolAddress((void**)&xlo, g_xlo);
    cudaGetSymbolAddress((void**)&Wqhi, g_Wqhi); cudaGetSymbolAddress((void**)&Wqlo, g_Wqlo);
    cudaGetSymbolAddress((void**)&Wkhi, g_Wkhi); cudaGetSymbolAddress((void**)&Wklo, g_Wklo);
    cudaGetSymbolAddress((void**)&Wvhi, g_Wvhi); cudaGetSymbolAddress((void**)&Wvlo, g_Wvlo);
    cudaGetSymbolAddress((void**)&Wohi, g_Wohi); cudaGetSymbolAddress((void**)&Wolo, g_Wolo);
    cudaGetSymbolAddress((void**)&qhi, g_qhi);   cudaGetSymbolAddress((void**)&qlo, g_qlo);
    cudaGetSymbolAddress((void**)&khi, g_khi);   cudaGetSymbolAddress((void**)&klo, g_klo);
    cudaGetSymbolAddress((void**)&vhi, g_vhi);   cudaGetSymbolAddress((void**)&vlo, g_vlo);
    cudaGetSymbolAddress((void**)&vThi, g_vThi); cudaGetSymbolAddress((void**)&vTlo, g_vTlo);
    cudaGetSymbolAddress((void**)&Ehi, g_Ehi);   cudaGetSymbolAddress((void**)&Elo, g_Elo);
    cudaGetSymbolAddress((void**)&chi, g_chi);   cudaGetSymbolAddress((void**)&clo, g_clo);
    cudaGetSymbolAddress((void**)&psum, g_psum); cudaGetSymbolAddress((void**)&rcpd, g_rcpd);

    cudaFuncSetAttribute(gemm_tc,  cudaFuncAttributeMaxDynamicSharedMemorySize, SMEM_TOTAL);
    cudaFuncSetAttribute(gemm_qkv, cudaFuncAttributeMaxDynamicSharedMemorySize, SMEM_TOTAL);

    const int M = BB * SS;  // 8192
    dim3 blk(NTHREADS);

    // 0) conversions: x + merged weights
    conv_split<<<(M * FF / 4 + 255) / 256, 256>>>(x, xhi, xlo, (long long)M * FF / 4);
    WconvP wp;
    wp.in[0] = Wq; wp.hi[0] = Wqhi; wp.lo[0] = Wqlo;
    wp.in[1] = Wk; wp.hi[1] = Wkhi; wp.lo[1] = Wklo;
    wp.in[2] = Wv; wp.hi[2] = Wvhi; wp.lo[2] = Wvlo;
    wp.in[3] = Wo; wp.hi[3] = Wohi; wp.lo[3] = Wolo;
    conv_split4<<<dim3((DKK * FF / 4 + 255) / 256, 4), 256>>>(wp, (long long)DKK * FF / 4);

    // 1) fused QKV projections -> bf16 hi/lo (+bias)
    QKVP p;
    p.Bh[0] = Wqhi; p.Bl[0] = Wqlo; p.bias[0] = bq; p.Oh[0] = qhi; p.Ol[0] = qlo;
    p.Bh[1] = Wkhi; p.Bl[1] = Wklo; p.bias[1] = bk; p.Oh[1] = khi; p.Ol[1] = klo;
    p.Bh[2] = Wvhi; p.Bl[2] = Wvlo; p.bias[2] = bv; p.Oh[2] = vhi; p.Ol[2] = vlo;
    dim3 g1(DKK / 128, M / 128, 3);
    gemm_qkv<<<g1, blk, SMEM_TOTAL>>>(xhi, xlo, p, FF, FF, FF, DKK);

    // 2) scores + fused exp epilogue -> unnormalized E hi/lo + column psums
    dim3 g2(SS / 128, SS / 128, BB);
    gemm_tc<<<g2, blk, SMEM_TOTAL>>>(qhi, qlo, khi, klo, nullptr, Ehi, Elo,
                                     nullptr, psum,
                                     DKK, DKK, DKK, SS,
                                     (long long)SS * DKK, (long long)SS * DKK,
                                     (long long)SS * SS, 1.0f / 32.0f);

    // 3) rcpd = 1/colsum (deterministic 16-way reduce)
    reduce_rcpd<<<BB * SS / 256, 256>>>(psum, rcpd);

    // 4) transpose v -> vT with rcp[k] folded in (per batch)
    dim3 g4(DKK / 32, SS / 32, BB);
    transpose_scale<<<g4, dim3(32, 8)>>>(vhi, vlo, rcpd, vThi, vTlo, SS, DKK);

    // 5) ctx = E @ V'  (NT with B = vT) -> bf16 hi/lo
    dim3 g5(DKK / 128, SS / 128, BB);
    gemm_tc<<<g5, blk, SMEM_TOTAL>>>(Ehi, Elo, vThi, vTlo, nullptr, chi, clo,
                                     nullptr, nullptr,
                                     SS, SS, SS, DKK,
                                     (long long)SS * SS, (long long)DKK * SS,
                                     (long long)SS * DKK, 1.0f);

    // 6) out = ctx @ Wo^T + bo -> fp32
    dim3 g6(FF / 128, M / 128, 1);
    gemm_tc<<<g6, blk, SMEM_TOTAL>>>(chi, clo, Wohi, Wolo, (float*)d_out,
                                     nullptr, nullptr, bo, nullptr,
                                     DKK, DKK, DKK, FF, 0, 0, 0, 1.0f);
}

// round 12
// speedup vs baseline: 1.3084x; 1.3084x over previous
#include <cuda_runtime.h>
#include <cuda_bf16.h>
#include <cuda_fp16.h>
#include <cstdint>

#define BB 4
#define SS 2048
#define FF 1024
#define DKK 1024

// ---------------- scratch (device globals; no allocs allowed) ----------------
__device__ __half         g_xhi[BB*SS*FF],  g_xlo[BB*SS*FF];     // x fp16 split
__device__ __half         g_Wq[DKK*FF], g_Wk[DKK*FF], g_Wv[DKK*FF], g_Wo[FF*DKK];
__device__ __nv_bfloat16  g_qhi[BB*SS*DKK], g_qlo[BB*SS*DKK];    // q bf16 split
__device__ __nv_bfloat16  g_khi[BB*SS*DKK], g_klo[BB*SS*DKK];    // k bf16 split
__device__ __nv_bfloat16  g_vhi[BB*SS*DKK], g_vlo[BB*SS*DKK];    // v bf16 split
__device__ __half         g_vT[BB*DKK*SS];                       // vT*rcp fp16
__device__ float          g_psum[(size_t)BB*16*SS];
__device__ float          g_rcpd[BB*SS];
__device__ __half         g_Ehi[(size_t)BB*SS*SS], g_Elo[(size_t)BB*SS*SS];
__device__ __half         g_chi[BB*SS*DKK], g_clo[BB*SS*DKK];    // ctx fp16 split

// ---------------- PTX helpers ----------------
__device__ __forceinline__ uint32_t smem_to_u32(const void* p) {
    uint32_t a;
    asm("{ .reg .u64 t; cvta.to.shared.u64 t, %1; cvt.u32.u64 %0, t; }" : "=r"(a) : "l"(p));
    return a;
}
__device__ __forceinline__ void cp16(uint32_t dst, const void* src) {
    asm volatile("cp.async.cg.shared.global [%0], [%1], 16;" :: "r"(dst), "l"(src));
}
#define CP_COMMIT() asm volatile("cp.async.commit_group;" ::: "memory")
template <int N> __device__ __forceinline__ void cp_wait() {
    asm volatile("cp.async.wait_group %0;" :: "n"(N) : "memory");
}
__device__ __forceinline__ void ldmx4(uint32_t* r, uint32_t addr) {
    asm volatile("ldmatrix.sync.aligned.m8n8.x4.shared.b16 {%0,%1,%2,%3}, [%4];"
        : "=r"(r[0]), "=r"(r[1]), "=r"(r[2]), "=r"(r[3]) : "r"(addr));
}
__device__ __forceinline__ void mma_bf16(float* c, const uint32_t* a, const uint32_t* b) {
    asm volatile(
        "mma.sync.aligned.m16n8k16.row.col.f32.bf16.bf16.f32 "
        "{%0,%1,%2,%3}, {%4,%5,%6,%7}, {%8,%9}, {%0,%1,%2,%3};"
        : "+f"(c[0]), "+f"(c[1]), "+f"(c[2]), "+f"(c[3])
        : "r"(a[0]), "r"(a[1]), "r"(a[2]), "r"(a[3]), "r"(b[0]), "r"(b[1]));
}
__device__ __forceinline__ void mma_f16(float* c, const uint32_t* a, const uint32_t* b) {
    asm volatile(
        "mma.sync.aligned.m16n8k16.row.col.f32.f16.f16.f32 "
        "{%0,%1,%2,%3}, {%4,%5,%6,%7}, {%8,%9}, {%0,%1,%2,%3};"
        : "+f"(c[0]), "+f"(c[1]), "+f"(c[2]), "+f"(c[3])
        : "r"(a[0]), "r"(a[1]), "r"(a[2]), "r"(a[3]), "r"(b[0]), "r"(b[1]));
}

// smem: rows of 32 elems (64B) @ stride 80B (conflict-free ldmatrix)
#define BK     32
#define STRB   80
#define PLANE  (128 * STRB)            // 10240 B
#define BUF3   (4 * PLANE)             // scores: 4 planes
#define SMEM3  (2 * BUF3)              // 81920 -> 2 CTAs/SM
#define BUF2   (3 * PLANE)             // fp16 2-term: 3 planes
#define SMEM2  (2 * BUF2)              // 61440 -> 2 CTAs/SM

#define NTHREADS 256

// ---------------------------------------------------------------------------
// gemm2 core: NT, A fp16 split (A0+A1), B fp16 single. 2 MMA sweeps.
// ---------------------------------------------------------------------------
__device__ __forceinline__ void gemm2_core(
    const __half* __restrict__ A0, const __half* __restrict__ A1,
    const __half* __restrict__ B,
    float* __restrict__ Cf,
    __nv_bfloat16* __restrict__ Qh, __nv_bfloat16* __restrict__ Ql,
    __half* __restrict__ Hh, __half* __restrict__ Hl,
    const float* __restrict__ bias,
    int K, int lda, int ldb, int ldc, size_t bm, size_t bn)
{
    extern __shared__ char smem[];
    uint32_t sbase = smem_to_u32(smem);
    int tid = threadIdx.x;
    int lane = tid & 31;
    int warp = tid >> 5;
    int m0w = (warp >> 1) * 32;
    int n0w = (warp & 1) * 64;

    float acc[2][8][4];
#pragma unroll
    for (int i = 0; i < 2; i++)
#pragma unroll
        for (int j = 0; j < 8; j++)
#pragma unroll
            for (int t = 0; t < 4; t++) acc[i][j][t] = 0.0f;

    int nch = K >> 5;

    auto prefetch = [&](int c) {
        int k0 = c << 5;
        uint32_t sb = sbase + (uint32_t)(c & 1) * BUF2;
#pragma unroll
        for (int it = 0; it < 2; it++) {
            int id = tid + it * NTHREADS;
            int row = id >> 2;
            int seg = id & 3;
            uint32_t doff = (uint32_t)(row * STRB + seg * 16);
            size_t ea = (size_t)row * lda + k0 + seg * 8;
            size_t eb = (size_t)row * ldb + k0 + seg * 8;
            cp16(sb + 0 * PLANE + doff, A0 + ea);
            cp16(sb + 1 * PLANE + doff, A1 + ea);
            cp16(sb + 2 * PLANE + doff, B + eb);
        }
    };

    int aRow = m0w + (lane & 15);
    uint32_t aColB = (uint32_t)((lane >> 4) * 16);
    int bRow = n0w + ((lane >> 4) << 3) + (lane & 7);
    uint32_t bColB = (uint32_t)(((lane >> 3) & 1) * 16);

    prefetch(0); CP_COMMIT();

    for (int c = 0; c < nch; c++) {
        cp_wait<0>();
        __syncthreads();
        if (c + 1 < nch) { prefetch(c + 1); CP_COMMIT(); }

        uint32_t sb = sbase + (uint32_t)(c & 1) * BUF2;
#pragma unroll
        for (int ks = 0; ks < 2; ks++) {
            uint32_t kB = (uint32_t)(ks * 32);
            uint32_t a_hi[2][4], a_lo[2][4];
#pragma unroll
            for (int mf = 0; mf < 2; mf++) {
                uint32_t off = (uint32_t)((aRow + mf * 16) * STRB) + kB + aColB;
                ldmx4(a_hi[mf], sb + 0 * PLANE + off);
                ldmx4(a_lo[mf], sb + 1 * PLANE + off);
            }
            uint32_t b[16];
#pragma unroll
            for (int ng = 0; ng < 4; ng++)
                ldmx4(&b[ng * 4], sb + 2 * PLANE +
                      (uint32_t)((bRow + ng * 16) * STRB) + kB + bColB);
#pragma unroll
            for (int mf = 0; mf < 2; mf++)
#pragma unroll
                for (int nf = 0; nf < 8; nf++)
                    mma_f16(acc[mf][nf], a_hi[mf], &b[nf * 2]);
#pragma unroll
            for (int mf = 0; mf < 2; mf++)
#pragma unroll
                for (int nf = 0; nf < 8; nf++)
                    mma_f16(acc[mf][nf], a_lo[mf], &b[nf * 2]);
        }
    }

    int gidr = lane >> 2;
    int tidq = lane & 3;
#pragma unroll
    for (int mf = 0; mf < 2; mf++) {
#pragma unroll
        for (int nf = 0; nf < 8; nf++) {
            size_t r0 = bm + m0w + mf * 16 + gidr;
            size_t r1 = r0 + 8;
            size_t col = bn + n0w + nf * 8 + tidq * 2;
            float b0 = bias ? bias[col] : 0.0f;
            float b1 = bias ? bias[col + 1] : 0.0f;
            float c00 = acc[mf][nf][0] + b0;
            float c01 = acc[mf][nf][1] + b1;
            float c10 = acc[mf][nf][2] + b0;
            float c11 = acc[mf][nf][3] + b1;
            if (Cf) {
                *(float2*)(Cf + r0 * ldc + col) = make_float2(c00, c01);
                *(float2*)(Cf + r1 * ldc + col) = make_float2(c10, c11);
            }
            if (Qh) {
                __nv_bfloat162 h0 = __floats2bfloat162_rn(c00, c01);
                __nv_bfloat162 h1 = __floats2bfloat162_rn(c10, c11);
                __nv_bfloat162 l0 = __floats2bfloat162_rn(
                    c00 - __bfloat162float(__low2bfloat16(h0)),
                    c01 - __bfloat162float(__high2bfloat16(h0)));
                __nv_bfloat162 l1 = __floats2bfloat162_rn(
                    c10 - __bfloat162float(__low2bfloat16(h1)),
                    c11 - __bfloat162float(__high2bfloat16(h1)));
                *(__nv_bfloat162*)(Qh + r0 * ldc + col) = h0;
                *(__nv_bfloat162*)(Qh + r1 * ldc + col) = h1;
                *(__nv_bfloat162*)(Ql + r0 * ldc + col) = l0;
                *(__nv_bfloat162*)(Ql + r1 * ldc + col) = l1;
            }
            if (Hh) {
                __half2 h0 = __floats2half2_rn(c00, c01);
                __half2 h1 = __floats2half2_rn(c10, c11);
                __half2 l0 = __floats2half2_rn(
                    c00 - __half2float(__low2half(h0)),
                    c01 - __half2float(__high2half(h0)));
                __half2 l1 = __floats2half2_rn(
                    c10 - __half2float(__low2half(h1)),
                    c11 - __half2float(__high2half(h1)));
                *(__half2*)(Hh + r0 * ldc + col) = h0;
                *(__half2*)(Hh + r1 * ldc + col) = h1;
                *(__half2*)(Hl + r0 * ldc + col) = l0;
                *(__half2*)(Hl + r1 * ldc + col) = l1;
            }
        }
    }
}

__global__ __launch_bounds__(NTHREADS, 2) void gemm2_tc(
    const __half* __restrict__ Ahi, const __half* __restrict__ Alo,
    const __half* __restrict__ B,
    float* __restrict__ Cf, __half* __restrict__ Hh, __half* __restrict__ Hl,
    const float* __restrict__ bias,
    int K, int lda, int ldb, int ldc,
    long long sA, long long sB, long long sC)
{
    int bz = blockIdx.z;
    size_t bm = (size_t)blockIdx.y * 128;
    size_t bn = (size_t)blockIdx.x * 128;
    gemm2_core(Ahi + (size_t)bz * sA + bm * lda, Alo + (size_t)bz * sA + bm * lda,
               B + (size_t)bz * sB + bn * ldb,
               Cf ? Cf + (size_t)bz * sC : nullptr,
               nullptr, nullptr,
               Hh ? Hh + (size_t)bz * sC : nullptr,
               Hl ? Hl + (size_t)bz * sC : nullptr,
               bias, K, lda, ldb, ldc, bm, bn);
}

struct QKVP {
    const __half* W[3];
    const float* bias[3];
    __nv_bfloat16* Oh[3];
    __nv_bfloat16* Ol[3];
};
__global__ __launch_bounds__(NTHREADS, 2) void gemm2_qkv(
    const __half* __restrict__ Ahi, const __half* __restrict__ Alo,
    QKVP p, int K, int lda, int ldb, int ldc)
{
    int z = blockIdx.z;
    size_t bm = (size_t)blockIdx.y * 128;
    size_t bn = (size_t)blockIdx.x * 128;
    gemm2_core(Ahi + bm * lda, Alo + bm * lda, p.W[z] + bn * ldb,
               nullptr, p.Oh[z], p.Ol[z], nullptr, nullptr,
               p.bias[z], K, lda, ldb, ldc, bm, bn);
}

// ---------------------------------------------------------------------------
// gemm3: scores, bf16 3-term, fused exp epilogue -> E fp16 hi/lo + psum.
// ---------------------------------------------------------------------------
__global__ __launch_bounds__(NTHREADS, 2) void gemm3_scores(
    const __nv_bfloat16* __restrict__ Qhi, const __nv_bfloat16* __restrict__ Qlo,
    const __nv_bfloat16* __restrict__ Khi, const __nv_bfloat16* __restrict__ Klo,
    __half* __restrict__ Ehi, __half* __restrict__ Elo,
    float* __restrict__ psum_all, float alpha)
{
    extern __shared__ char smem[];
    uint32_t sbase = smem_to_u32(smem);
    int tid = threadIdx.x;
    int lane = tid & 31;
    int warp = tid >> 5;
    int m0w = (warp >> 1) * 32;
    int n0w = (warp & 1) * 64;

    int bz = blockIdx.z;
    size_t bm = (size_t)blockIdx.y * 128;
    size_t bn = (size_t)blockIdx.x * 128;
    const __nv_bfloat16* A0 = Qhi + (size_t)bz * SS * DKK + bm * DKK;
    const __nv_bfloat16* A1 = Qlo + (size_t)bz * SS * DKK + bm * DKK;
    const __nv_bfloat16* B0 = Khi + (size_t)bz * SS * DKK + bn * DKK;
    const __nv_bfloat16* B1 = Klo + (size_t)bz * SS * DKK + bn * DKK;
    __half* Eh = Ehi + (size_t)bz * SS * SS;
    __half* El = Elo + (size_t)bz * SS * SS;
    float* psum = psum_all + ((size_t)bz * gridDim.y + blockIdx.y) * SS + bn;

    float acc[2][8][4];
#pragma unroll
    for (int i = 0; i < 2; i++)
#pragma unroll
        for (int j = 0; j < 8; j++)
#pragma unroll
            for (int t = 0; t < 4; t++) acc[i][j][t] = 0.0f;

    const int nch = DKK >> 5;

    auto prefetch = [&](int c) {
        int k0 = c << 5;
        uint32_t sb = sbase + (uint32_t)(c & 1) * BUF3;
#pragma unroll
        for (int it = 0; it < 2; it++) {
            int id = tid + it * NTHREADS;
            int row = id >> 2;
            int seg = id & 3;
            uint32_t doff = (uint32_t)(row * STRB + seg * 16);
            size_t ea = (size_t)row * DKK + k0 + seg * 8;
            cp16(sb + 0 * PLANE + doff, A0 + ea);
            cp16(sb + 1 * PLANE + doff, A1 + ea);
            cp16(sb + 2 * PLANE + doff, B0 + ea);
            cp16(sb + 3 * PLANE + doff, B1 + ea);
        }
    };

    int aRow = m0w + (lane & 15);
    uint32_t aColB = (uint32_t)((lane >> 4) * 16);
    int bRow = n0w + ((lane >> 4) << 3) + (lane & 7);
    uint32_t bColB = (uint32_t)(((lane >> 3) & 1) * 16);

    prefetch(0); CP_COMMIT();

    for (int c = 0; c < nch; c++) {
        cp_wait<0>();
        __syncthreads();
        if (c + 1 < nch) { prefetch(c + 1); CP_COMMIT(); }

        uint32_t sb = sbase + (uint32_t)(c & 1) * BUF3;
#pragma unroll
        for (int ks = 0; ks < 2; ks++) {
            uint32_t kB = (uint32_t)(ks * 32);
            uint32_t a_hi[2][4], a_lo[2][4];
#pragma unroll
            for (int mf = 0; mf < 2; mf++) {
                uint32_t off = (uint32_t)((aRow + mf * 16) * STRB) + kB + aColB;
                ldmx4(a_hi[mf], sb + 0 * PLANE + off);
                ldmx4(a_lo[mf], sb + 1 * PLANE + off);
            }
            uint32_t b_hi[16], b_lo[16];
#pragma unroll
            for (int ng = 0; ng < 4; ng++) {
                uint32_t off = (uint32_t)((bRow + ng * 16) * STRB) + kB + bColB;
                ldmx4(&b_hi[ng * 4], sb + 2 * PLANE + off);
                ldmx4(&b_lo[ng * 4], sb + 3 * PLANE + off);
            }
#pragma unroll
            for (int mf = 0; mf < 2; mf++)
#pragma unroll
                for (int nf = 0; nf < 8; nf++)
                    mma_bf16(acc[mf][nf], a_hi[mf], &b_hi[nf * 2]);
#pragma unroll
            for (int mf = 0; mf < 2; mf++)
#pragma unroll
                for (int nf = 0; nf < 8; nf++)
                    mma_bf16(acc[mf][nf], a_hi[mf], &b_lo[nf * 2]);
#pragma unroll
            for (int mf = 0; mf < 2; mf++)
#pragma unroll
                for (int nf = 0; nf < 8; nf++)
                    mma_bf16(acc[mf][nf], a_lo[mf], &b_hi[nf * 2]);
        }
    }

    int gidr = lane >> 2;
    int tidq = lane & 3;
    float cs[8][2];
#pragma unroll
    for (int nf = 0; nf < 8; nf++) { cs[nf][0] = 0.0f; cs[nf][1] = 0.0f; }
#pragma unroll
    for (int mf = 0; mf < 2; mf++) {
#pragma unroll
        for (int nf = 0; nf < 8; nf++) {
            size_t r0 = bm + m0w + mf * 16 + gidr;
            size_t r1 = r0 + 8;
            size_t col = bn + n0w + nf * 8 + tidq * 2;
            float e00 = __expf(acc[mf][nf][0] * alpha);
            float e01 = __expf(acc[mf][nf][1] * alpha);
            float e10 = __expf(acc[mf][nf][2] * alpha);
            float e11 = __expf(acc[mf][nf][3] * alpha);
            cs[nf][0] += e00 + e10;
            cs[nf][1] += e01 + e11;
            __half2 h0 = __floats2half2_rn(e00, e01);
            __half2 h1 = __floats2half2_rn(e10, e11);
            __half2 l0 = __floats2half2_rn(
                e00 - __half2float(__low2half(h0)),
                e01 - __half2float(__high2half(h0)));
            __half2 l1 = __floats2half2_rn(
                e10 - __half2float(__low2half(h1)),
                e11 - __half2float(__high2half(h1)));
            *(__half2*)(Eh + r0 * SS + col) = h0;
            *(__half2*)(Eh + r1 * SS + col) = h1;
            *(__half2*)(El + r0 * SS + col) = l0;
            *(__half2*)(El + r1 * SS + col) = l1;
        }
    }
#pragma unroll
    for (int nf = 0; nf < 8; nf++)
#pragma unroll
        for (int t = 0; t < 2; t++) {
            float v = cs[nf][t];
            v += __shfl_xor_sync(0xffffffff, v, 4);
            v += __shfl_xor_sync(0xffffffff, v, 8);
            v += __shfl_xor_sync(0xffffffff, v, 16);
            cs[nf][t] = v;
        }
    float* sred = (float*)smem;
    __syncthreads();
    if (gidr == 0) {
#pragma unroll
        for (int nf = 0; nf < 8; nf++) {
            sred[(warp >> 1) * 128 + n0w + nf * 8 + tidq * 2 + 0] = cs[nf][0];
            sred[(warp >> 1) * 128 + n0w + nf * 8 + tidq * 2 + 1] = cs[nf][1];
        }
    }
    __syncthreads();
    if (tid < 128)
        psum[tid] = sred[tid] + sred[128 + tid] + sred[256 + tid] + sred[384 + tid];
}

// ---------------------------------------------------------------------------
__global__ __launch_bounds__(256) void conv_split_h(
    const float* __restrict__ in, __half* __restrict__ hi,
    __half* __restrict__ lo, long long n4)
{
    long long i = (long long)blockIdx.x * blockDim.x + threadIdx.x;
    if (i >= n4) return;
    float4 v = ((const float4*)in)[i];
    __half2 h0 = __floats2half2_rn(v.x, v.y);
    __half2 h1 = __floats2half2_rn(v.z, v.w);
    float r0 = v.x - __half2float(__low2half(h0));
    float r1 = v.y - __half2float(__high2half(h0));
    float r2 = v.z - __half2float(__low2half(h1));
    float r3 = v.w - __half2float(__high2half(h1));
    ((__half2*)hi)[2 * i] = h0;
    ((__half2*)hi)[2 * i + 1] = h1;
    ((__half2*)lo)[2 * i] = __floats2half2_rn(r0, r1);
    ((__half2*)lo)[2 * i + 1] = __floats2half2_rn(r2, r3);
}

struct WconvP {
    const float* in[4];
    __half* out[4];
};
__global__ __launch_bounds__(256) void conv_w4(WconvP p, long long n4)
{
    int w = blockIdx.y;
    long long i = (long long)blockIdx.x * blockDim.x + threadIdx.x;
    if (i >= n4) return;
    float4 v = ((const float4*)p.in[w])[i];
    ((__half2*)p.out[w])[2 * i] = __floats2half2_rn(v.x, v.y);
    ((__half2*)p.out[w])[2 * i + 1] = __floats2half2_rn(v.z, v.w);
}

__global__ __launch_bounds__(256) void reduce_rcpd(
    const float* __restrict__ psum, float* __restrict__ rcpd)
{
    int i = blockIdx.x * blockDim.x + threadIdx.x;
    int b = i >> 11;
    int col = i & (SS - 1);
    const float* p = psum + (size_t)b * 16 * SS + col;
    float s = 0.0f;
#pragma unroll
    for (int t = 0; t < 16; t++) s += p[(size_t)t * SS];
    rcpd[i] = 1.0f / s;
}

__global__ __launch_bounds__(256) void transpose_scale(
    const __nv_bfloat16* __restrict__ ihi, const __nv_bfloat16* __restrict__ ilo,
    const float* __restrict__ rcpd, __half* __restrict__ oT,
    int rows, int cols)
{
    __shared__ __half t0[32][33];
    int z = blockIdx.z;
    size_t ioff = (size_t)z * rows * cols;
    int c0 = blockIdx.x * 32, r0 = blockIdx.y * 32;
    int tx = threadIdx.x, ty = threadIdx.y;

#pragma unroll
    for (int j = 0; j < 32; j += 8) {
        int r = r0 + ty + j;
        float rcp = rcpd[(size_t)z * rows + r];
        size_t idx = ioff + (size_t)r * cols + c0 + tx;
        float v = (__bfloat162float(ihi[idx]) + __bfloat162float(ilo[idx])) * rcp;
        t0[ty + j][tx] = __float2half(v);
    }
    __syncthreads();
#pragma unroll
    for (int j = 0; j < 32; j += 8) {
        size_t odx = ioff + (size_t)(c0 + ty + j) * rows + r0 + tx;
        oT[odx] = t0[tx][ty + j];
    }
}

// ---------------------------------------------------------------------------
extern "C" void kernel_launch(void* const* d_in, const int* in_sizes, int n_in,
                              void* d_out, int out_size)
{
    const float* x  = (const float*)d_in[0];
    const float* Wq = (const float*)d_in[1];
    const float* bq = (const float*)d_in[2];
    const float* Wk = (const float*)d_in[3];
    const float* bk = (const float*)d_in[4];
    const float* Wv = (const float*)d_in[5];
    const float* bv = (const float*)d_in[6];
    const float* Wo = (const float*)d_in[7];
    const float* bo = (const float*)d_in[8];

    __half *xhi, *xlo, *wq, *wk, *wv, *wo, *vT, *Ehi, *Elo, *chi, *clo;
    __nv_bfloat16 *qhi, *qlo, *khi, *klo, *vhi, *vlo;
    float *psum, *rcpd;
    cudaGetSymbolAddress((void**)&xhi, g_xhi);   cudaGetSymbolAddress((void**)&xlo, g_xlo);
    cudaGetSymbolAddress((void**)&wq, g_Wq);     cudaGetSymbolAddress((void**)&wk, g_Wk);
    cudaGetSymbolAddress((void**)&wv, g_Wv);     cudaGetSymbolAddress((void**)&wo, g_Wo);
    cudaGetSymbolAddress((void**)&qhi, g_qhi);   cudaGetSymbolAddress((void**)&qlo, g_qlo);
    cudaGetSymbolAddress((void**)&khi, g_khi);   cudaGetSymbolAddress((void**)&klo, g_klo);
    cudaGetSymbolAddress((void**)&vhi, g_vhi);   cudaGetSymbolAddress((void**)&vlo, g_vlo);
    cudaGetSymbolAddress((void**)&vT, g_vT);
    cudaGetSymbolAddress((void**)&Ehi, g_Ehi);   cudaGetSymbolAddress((void**)&Elo, g_Elo);
    cudaGetSymbolAddress((void**)&chi, g_chi);   cudaGetSymbolAddress((void**)&clo, g_clo);
    cudaGetSymbolAddress((void**)&psum, g_psum); cudaGetSymbolAddress((void**)&rcpd, g_rcpd);

    cudaFuncSetAttribute(gemm2_tc,     cudaFuncAttributeMaxDynamicSharedMemorySize, SMEM2);
    cudaFuncSetAttribute(gemm2_qkv,    cudaFuncAttributeMaxDynamicSharedMemorySize, SMEM2);
    cudaFuncSetAttribute(gemm3_scores, cudaFuncAttributeMaxDynamicSharedMemorySize, SMEM3);

    const int M = BB * SS;  // 8192
    dim3 blk(NTHREADS);

    // 0) conversions
    conv_split_h<<<(M * FF / 4 + 255) / 256, 256>>>(x, xhi, xlo, (long long)M * FF / 4);
    WconvP wp;
    wp.in[0] = Wq; wp.out[0] = wq;
    wp.in[1] = Wk; wp.out[1] = wk;
    wp.in[2] = Wv; wp.out[2] = wv;
    wp.in[3] = Wo; wp.out[3] = wo;
    conv_w4<<<dim3((DKK * FF / 4 + 255) / 256, 4), 256>>>(wp, (long long)DKK * FF / 4);

    // 1) fused QKV (fp16 2-term) -> q,k,v bf16 hi/lo (+bias)
    QKVP p;
    p.W[0] = wq; p.bias[0] = bq; p.Oh[0] = qhi; p.Ol[0] = qlo;
    p.W[1] = wk; p.bias[1] = bk; p.Oh[1] = khi; p.Ol[1] = klo;
    p.W[2] = wv; p.bias[2] = bv; p.Oh[2] = vhi; p.Ol[2] = vlo;
    dim3 g1(DKK / 128, M / 128, 3);
    gemm2_qkv<<<g1, blk, SMEM2>>>(xhi, xlo, p, FF, FF, FF, DKK);

    // 2) scores (bf16 3-term) + fused exp -> E fp16 hi/lo + col psums
    dim3 g2(SS / 128, SS / 128, BB);
    gemm3_scores<<<g2, blk, SMEM3>>>(qhi, qlo, khi, klo, Ehi, Elo, psum,
                                     1.0f / 32.0f);

    // 3) rcpd = 1/colsum
    reduce_rcpd<<<BB * SS / 256, 256>>>(psum, rcpd);

    // 4) transpose v -> vT (fp16 single) with rcp folded
    dim3 g4(DKK / 32, SS / 32, BB);
    transpose_scale<<<g4, dim3(32, 8)>>>(vhi, vlo, rcpd, vT, SS, DKK);

    // 5) ctx = E @ V' (fp16 2-term) -> ctx fp16 hi/lo
    dim3 g5(DKK / 128, SS / 128, BB);
    gemm2_tc<<<g5, blk, SMEM2>>>(Ehi, Elo, vT, nullptr, chi, clo, nullptr,
                                 SS, SS, SS, DKK,
                                 (long long)SS * SS, (long long)DKK * SS,
                                 (long long)SS * DKK);

    // 6) out = ctx @ Wo^T + bo (fp16 2-term) -> fp32
    dim3 g6(FF / 128, M / 128, 1);
    gemm2_tc<<<g6, blk, SMEM2>>>(chi, clo, wo, (float*)d_out, nullptr, nullptr,
                                 bo, DKK, DKK, DKK, FF, 0, 0, 0);
}

// round 13
// speedup vs baseline: 1.4433x; 1.1031x over previous
#include <cuda_runtime.h>
#include <cuda_bf16.h>
#include <cuda_fp16.h>
#include <cstdint>

#define BB 4
#define SS 2048
#define FF 1024
#define DKK 1024

// ---------------- scratch (device globals; no allocs allowed) ----------------
__device__ __half  g_xhi[BB*SS*FF],  g_xlo[BB*SS*FF];      // x fp16 split
__device__ __half  g_Wq[DKK*FF], g_Wk[DKK*FF], g_Wv[DKK*FF], g_Wo[FF*DKK];
__device__ __half  g_qhi[BB*SS*DKK], g_qlo[BB*SS*DKK];     // q fp16 split
__device__ __half  g_ks[BB*SS*DKK];                        // k fp16 single
__device__ __half  g_vhi[BB*SS*DKK], g_vlo[BB*SS*DKK];     // v fp16 split
__device__ __half  g_vT[BB*DKK*SS];                        // vT*rcp fp16 single
__device__ float   g_psum[(size_t)BB*16*SS];
__device__ float   g_rcpd[BB*SS];
__device__ __half  g_Ehi[(size_t)BB*SS*SS], g_Elo[(size_t)BB*SS*SS];
__device__ __half  g_chi[BB*SS*DKK], g_clo[BB*SS*DKK];     // ctx fp16 split

// ---------------- PTX helpers ----------------
__device__ __forceinline__ uint32_t smem_to_u32(const void* p) {
    uint32_t a;
    asm("{ .reg .u64 t; cvta.to.shared.u64 t, %1; cvt.u32.u64 %0, t; }" : "=r"(a) : "l"(p));
    return a;
}
__device__ __forceinline__ void cp16(uint32_t dst, const void* src) {
    asm volatile("cp.async.cg.shared.global [%0], [%1], 16;" :: "r"(dst), "l"(src));
}
#define CP_COMMIT() asm volatile("cp.async.commit_group;" ::: "memory")
template <int N> __device__ __forceinline__ void cp_wait() {
    asm volatile("cp.async.wait_group %0;" :: "n"(N) : "memory");
}
__device__ __forceinline__ void ldmx4(uint32_t* r, uint32_t addr) {
    asm volatile("ldmatrix.sync.aligned.m8n8.x4.shared.b16 {%0,%1,%2,%3}, [%4];"
        : "=r"(r[0]), "=r"(r[1]), "=r"(r[2]), "=r"(r[3]) : "r"(addr));
}
__device__ __forceinline__ void mma_f16(float* c, const uint32_t* a, const uint32_t* b) {
    asm volatile(
        "mma.sync.aligned.m16n8k16.row.col.f32.f16.f16.f32 "
        "{%0,%1,%2,%3}, {%4,%5,%6,%7}, {%8,%9}, {%0,%1,%2,%3};"
        : "+f"(c[0]), "+f"(c[1]), "+f"(c[2]), "+f"(c[3])
        : "r"(a[0]), "r"(a[1]), "r"(a[2]), "r"(a[3]), "r"(b[0]), "r"(b[1]));
}

// smem: rows of 32 elems (64B) @ stride 80B (conflict-free ldmatrix)
#define BK     32
#define STRB   80
#define PLANE  (128 * STRB)            // 10240 B
#define BUF2   (3 * PLANE)             // 3 planes (A hi, A lo, B)
#define SMEM2  (2 * BUF2)              // 61440 -> 2 CTAs/SM

#define NTHREADS 256

// ---------------------------------------------------------------------------
// gemm2 core: NT, A fp16 split (A0+A1), B fp16 single, 2 fp16 MMA sweeps.
// 8 warps (4x2), warp tile 32x64, CTA tile 128x128, BK=32, 2-stage pipeline.
// EXP=0: outputs Cf (fp32 + bias) or fp16 pair Hh/Hl (Hl may be null -> single).
// EXP=1: outputs E=exp(alpha*acc) as fp16 pair + per-tile column sums to psum.
// ---------------------------------------------------------------------------
template <int EXP>
__device__ __forceinline__ void gemm2_core(
    const __half* __restrict__ A0, const __half* __restrict__ A1,
    const __half* __restrict__ B,
    float* __restrict__ Cf, __half* __restrict__ Hh, __half* __restrict__ Hl,
    const float* __restrict__ bias, float* __restrict__ psum, float alpha,
    int K, int lda, int ldb, int ldc, size_t bm, size_t bn)
{
    extern __shared__ char smem[];
    uint32_t sbase = smem_to_u32(smem);
    int tid = threadIdx.x;
    int lane = tid & 31;
    int warp = tid >> 5;
    int m0w = (warp >> 1) * 32;
    int n0w = (warp & 1) * 64;

    float acc[2][8][4];
#pragma unroll
    for (int i = 0; i < 2; i++)
#pragma unroll
        for (int j = 0; j < 8; j++)
#pragma unroll
            for (int t = 0; t < 4; t++) acc[i][j][t] = 0.0f;

    int nch = K >> 5;

    auto prefetch = [&](int c) {
        int k0 = c << 5;
        uint32_t sb = sbase + (uint32_t)(c & 1) * BUF2;
#pragma unroll
        for (int it = 0; it < 2; it++) {
            int id = tid + it * NTHREADS;
            int row = id >> 2;
            int seg = id & 3;
            uint32_t doff = (uint32_t)(row * STRB + seg * 16);
            size_t ea = (size_t)row * lda + k0 + seg * 8;
            size_t eb = (size_t)row * ldb + k0 + seg * 8;
            cp16(sb + 0 * PLANE + doff, A0 + ea);
            cp16(sb + 1 * PLANE + doff, A1 + ea);
            cp16(sb + 2 * PLANE + doff, B + eb);
        }
    };

    int aRow = m0w + (lane & 15);
    uint32_t aColB = (uint32_t)((lane >> 4) * 16);
    int bRow = n0w + ((lane >> 4) << 3) + (lane & 7);
    uint32_t bColB = (uint32_t)(((lane >> 3) & 1) * 16);

    prefetch(0); CP_COMMIT();

    for (int c = 0; c < nch; c++) {
        cp_wait<0>();
        __syncthreads();
        if (c + 1 < nch) { prefetch(c + 1); CP_COMMIT(); }

        uint32_t sb = sbase + (uint32_t)(c & 1) * BUF2;
#pragma unroll
        for (int ks = 0; ks < 2; ks++) {
            uint32_t kB = (uint32_t)(ks * 32);
            uint32_t a_hi[2][4], a_lo[2][4];
#pragma unroll
            for (int mf = 0; mf < 2; mf++) {
                uint32_t off = (uint32_t)((aRow + mf * 16) * STRB) + kB + aColB;
                ldmx4(a_hi[mf], sb + 0 * PLANE + off);
                ldmx4(a_lo[mf], sb + 1 * PLANE + off);
            }
            uint32_t b[16];
#pragma unroll
            for (int ng = 0; ng < 4; ng++)
                ldmx4(&b[ng * 4], sb + 2 * PLANE +
                      (uint32_t)((bRow + ng * 16) * STRB) + kB + bColB);
#pragma unroll
            for (int mf = 0; mf < 2; mf++)
#pragma unroll
                for (int nf = 0; nf < 8; nf++)
                    mma_f16(acc[mf][nf], a_hi[mf], &b[nf * 2]);
#pragma unroll
            for (int mf = 0; mf < 2; mf++)
#pragma unroll
                for (int nf = 0; nf < 8; nf++)
                    mma_f16(acc[mf][nf], a_lo[mf], &b[nf * 2]);
        }
    }

    int gidr = lane >> 2;
    int tidq = lane & 3;

    if (EXP) {
        float cs[8][2];
#pragma unroll
        for (int nf = 0; nf < 8; nf++) { cs[nf][0] = 0.0f; cs[nf][1] = 0.0f; }
#pragma unroll
        for (int mf = 0; mf < 2; mf++) {
#pragma unroll
            for (int nf = 0; nf < 8; nf++) {
                size_t r0 = bm + m0w + mf * 16 + gidr;
                size_t r1 = r0 + 8;
                size_t col = bn + n0w + nf * 8 + tidq * 2;
                float e00 = __expf(acc[mf][nf][0] * alpha);
                float e01 = __expf(acc[mf][nf][1] * alpha);
                float e10 = __expf(acc[mf][nf][2] * alpha);
                float e11 = __expf(acc[mf][nf][3] * alpha);
                cs[nf][0] += e00 + e10;
                cs[nf][1] += e01 + e11;
                __half2 h0 = __floats2half2_rn(e00, e01);
                __half2 h1 = __floats2half2_rn(e10, e11);
                __half2 l0 = __floats2half2_rn(
                    e00 - __half2float(__low2half(h0)),
                    e01 - __half2float(__high2half(h0)));
                __half2 l1 = __floats2half2_rn(
                    e10 - __half2float(__low2half(h1)),
                    e11 - __half2float(__high2half(h1)));
                *(__half2*)(Hh + r0 * ldc + col) = h0;
                *(__half2*)(Hh + r1 * ldc + col) = h1;
                *(__half2*)(Hl + r0 * ldc + col) = l0;
                *(__half2*)(Hl + r1 * ldc + col) = l1;
            }
        }
#pragma unroll
        for (int nf = 0; nf < 8; nf++)
#pragma unroll
            for (int t = 0; t < 2; t++) {
                float v = cs[nf][t];
                v += __shfl_xor_sync(0xffffffff, v, 4);
                v += __shfl_xor_sync(0xffffffff, v, 8);
                v += __shfl_xor_sync(0xffffffff, v, 16);
                cs[nf][t] = v;
            }
        float* sred = (float*)smem;
        __syncthreads();
        if (gidr == 0) {
#pragma unroll
            for (int nf = 0; nf < 8; nf++) {
                sred[(warp >> 1) * 128 + n0w + nf * 8 + tidq * 2 + 0] = cs[nf][0];
                sred[(warp >> 1) * 128 + n0w + nf * 8 + tidq * 2 + 1] = cs[nf][1];
            }
        }
        __syncthreads();
        if (tid < 128)
            psum[tid] = sred[tid] + sred[128 + tid] + sred[256 + tid] + sred[384 + tid];
        return;
    }

#pragma unroll
    for (int mf = 0; mf < 2; mf++) {
#pragma unroll
        for (int nf = 0; nf < 8; nf++) {
            size_t r0 = bm + m0w + mf * 16 + gidr;
            size_t r1 = r0 + 8;
            size_t col = bn + n0w + nf * 8 + tidq * 2;
            float b0 = bias ? bias[col] : 0.0f;
            float b1 = bias ? bias[col + 1] : 0.0f;
            float c00 = acc[mf][nf][0] + b0;
            float c01 = acc[mf][nf][1] + b1;
            float c10 = acc[mf][nf][2] + b0;
            float c11 = acc[mf][nf][3] + b1;
            if (Cf) {
                *(float2*)(Cf + r0 * ldc + col) = make_float2(c00, c01);
                *(float2*)(Cf + r1 * ldc + col) = make_float2(c10, c11);
            }
            if (Hh) {
                __half2 h0 = __floats2half2_rn(c00, c01);
                __half2 h1 = __floats2half2_rn(c10, c11);
                *(__half2*)(Hh + r0 * ldc + col) = h0;
                *(__half2*)(Hh + r1 * ldc + col) = h1;
                if (Hl) {
                    __half2 l0 = __floats2half2_rn(
                        c00 - __half2float(__low2half(h0)),
                        c01 - __half2float(__high2half(h0)));
                    __half2 l1 = __floats2half2_rn(
                        c10 - __half2float(__low2half(h1)),
                        c11 - __half2float(__high2half(h1)));
                    *(__half2*)(Hl + r0 * ldc + col) = l0;
                    *(__half2*)(Hl + r1 * ldc + col) = l1;
                }
            }
        }
    }
}

// Generic batched fp16 2-term NT GEMM (standard epilogue)
__global__ __launch_bounds__(NTHREADS, 2) void gemm2_tc(
    const __half* __restrict__ Ahi, const __half* __restrict__ Alo,
    const __half* __restrict__ B,
    float* __restrict__ Cf, __half* __restrict__ Hh, __half* __restrict__ Hl,
    const float* __restrict__ bias,
    int K, int lda, int ldb, int ldc,
    long long sA, long long sB, long long sC)
{
    int bz = blockIdx.z;
    size_t bm = (size_t)blockIdx.y * 128;
    size_t bn = (size_t)blockIdx.x * 128;
    gemm2_core<0>(Ahi + (size_t)bz * sA + bm * lda, Alo + (size_t)bz * sA + bm * lda,
                  B + (size_t)bz * sB + bn * ldb,
                  Cf ? Cf + (size_t)bz * sC : nullptr,
                  Hh ? Hh + (size_t)bz * sC : nullptr,
                  Hl ? Hl + (size_t)bz * sC : nullptr,
                  bias, nullptr, 0.0f, K, lda, ldb, ldc, bm, bn);
}

// Scores: fp16 2-term with fused exp epilogue (A=q split, B=k single)
__global__ __launch_bounds__(NTHREADS, 2) void gemm2_scores(
    const __half* __restrict__ Qhi, const __half* __restrict__ Qlo,
    const __half* __restrict__ Ks,
    __half* __restrict__ Ehi, __half* __restrict__ Elo,
    float* __restrict__ psum_all, float alpha)
{
    int bz = blockIdx.z;
    size_t bm = (size_t)blockIdx.y * 128;
    size_t bn = (size_t)blockIdx.x * 128;
    float* ps = psum_all + ((size_t)bz * gridDim.y + blockIdx.y) * SS + bn;
    gemm2_core<1>(Qhi + (size_t)bz * SS * DKK + bm * DKK,
                  Qlo + (size_t)bz * SS * DKK + bm * DKK,
                  Ks + (size_t)bz * SS * DKK + bn * DKK,
                  nullptr,
                  Ehi + (size_t)bz * SS * SS,
                  Elo + (size_t)bz * SS * SS,
                  nullptr, ps, alpha, DKK, DKK, DKK, SS, bm, bn);
}

// Fused QKV: z selects weight + output (q,v = fp16 pair; k = fp16 single)
struct QKVP {
    const __half* W[3];
    const float* bias[3];
    __half* Oh[3];
    __half* Ol[3];   // null for k -> single-precision store
};
__global__ __launch_bounds__(NTHREADS, 2) void gemm2_qkv(
    const __half* __restrict__ Ahi, const __half* __restrict__ Alo,
    QKVP p, int K, int lda, int ldb, int ldc)
{
    int z = blockIdx.z;
    size_t bm = (size_t)blockIdx.y * 128;
    size_t bn = (size_t)blockIdx.x * 128;
    gemm2_core<0>(Ahi + bm * lda, Alo + bm * lda, p.W[z] + bn * ldb,
                  nullptr, p.Oh[z], p.Ol[z],
                  p.bias[z], nullptr, 0.0f, K, lda, ldb, ldc, bm, bn);
}

// ---------------------------------------------------------------------------
__global__ __launch_bounds__(256) void conv_split_h(
    const float* __restrict__ in, __half* __restrict__ hi,
    __half* __restrict__ lo, long long n4)
{
    long long i = (long long)blockIdx.x * blockDim.x + threadIdx.x;
    if (i >= n4) return;
    float4 v = ((const float4*)in)[i];
    __half2 h0 = __floats2half2_rn(v.x, v.y);
    __half2 h1 = __floats2half2_rn(v.z, v.w);
    float r0 = v.x - __half2float(__low2half(h0));
    float r1 = v.y - __half2float(__high2half(h0));
    float r2 = v.z - __half2float(__low2half(h1));
    float r3 = v.w - __half2float(__high2half(h1));
    ((__half2*)hi)[2 * i] = h0;
    ((__half2*)hi)[2 * i + 1] = h1;
    ((__half2*)lo)[2 * i] = __floats2half2_rn(r0, r1);
    ((__half2*)lo)[2 * i + 1] = __floats2half2_rn(r2, r3);
}

struct WconvP {
    const float* in[4];
    __half* out[4];
};
__global__ __launch_bounds__(256) void conv_w4(WconvP p, long long n4)
{
    int w = blockIdx.y;
    long long i = (long long)blockIdx.x * blockDim.x + threadIdx.x;
    if (i >= n4) return;
    float4 v = ((const float4*)p.in[w])[i];
    ((__half2*)p.out[w])[2 * i] = __floats2half2_rn(v.x, v.y);
    ((__half2*)p.out[w])[2 * i + 1] = __floats2half2_rn(v.z, v.w);
}

__global__ __launch_bounds__(256) void reduce_rcpd(
    const float* __restrict__ psum, float* __restrict__ rcpd)
{
    int i = blockIdx.x * blockDim.x + threadIdx.x;
    int b = i >> 11;
    int col = i & (SS - 1);
    const float* p = psum + (size_t)b * 16 * SS + col;
    float s = 0.0f;
#pragma unroll
    for (int t = 0; t < 16; t++) s += p[(size_t)t * SS];
    rcpd[i] = 1.0f / s;
}

// transpose + scale: vT[d][k] = (vhi+vlo)[k][d] * rcp[k] as single fp16
__global__ __launch_bounds__(256) void transpose_scale(
    const __half* __restrict__ ihi, const __half* __restrict__ ilo,
    const float* __restrict__ rcpd, __half* __restrict__ oT,
    int rows, int cols)
{
    __shared__ __half t0[32][33];
    int z = blockIdx.z;
    size_t ioff = (size_t)z * rows * cols;
    int c0 = blockIdx.x * 32, r0 = blockIdx.y * 32;
    int tx = threadIdx.x, ty = threadIdx.y;

#pragma unroll
    for (int j = 0; j < 32; j += 8) {
        int r = r0 + ty + j;
        float rcp = rcpd[(size_t)z * rows + r];
        size_t idx = ioff + (size_t)r * cols + c0 + tx;
        float v = (__half2float(ihi[idx]) + __half2float(ilo[idx])) * rcp;
        t0[ty + j][tx] = __float2half(v);
    }
    __syncthreads();
#pragma unroll
    for (int j = 0; j < 32; j += 8) {
        size_t odx = ioff + (size_t)(c0 + ty + j) * rows + r0 + tx;
        oT[odx] = t0[tx][ty + j];
    }
}

// ---------------------------------------------------------------------------
extern "C" void kernel_launch(void* const* d_in, const int* in_sizes, int n_in,
                              void* d_out, int out_size)
{
    const float* x  = (const float*)d_in[0];
    const float* Wq = (const float*)d_in[1];
    const float* bq = (const float*)d_in[2];
    const float* Wk = (const float*)d_in[3];
    const float* bk = (const float*)d_in[4];
    const float* Wv = (const float*)d_in[5];
    const float* bv = (const float*)d_in[6];
    const float* Wo = (const float*)d_in[7];
    const float* bo = (const float*)d_in[8];

    __half *xhi, *xlo, *wq, *wk, *wv, *wo, *qhi, *qlo, *ks, *vhi, *vlo, *vT;
    __half *Ehi, *Elo, *chi, *clo;
    float *psum, *rcpd;
    cudaGetSymbolAddress((void**)&xhi, g_xhi);   cudaGetSymbolAddress((void**)&xlo, g_xlo);
    cudaGetSymbolAddress((void**)&wq, g_Wq);     cudaGetSymbolAddress((void**)&wk, g_Wk);
    cudaGetSymbolAddress((void**)&wv, g_Wv);     cudaGetSymbolAddress((void**)&wo, g_Wo);
    cudaGetSymbolAddress((void**)&qhi, g_qhi);   cudaGetSymbolAddress((void**)&qlo, g_qlo);
    cudaGetSymbolAddress((void**)&ks, g_ks);
    cudaGetSymbolAddress((void**)&vhi, g_vhi);   cudaGetSymbolAddress((void**)&vlo, g_vlo);
    cudaGetSymbolAddress((void**)&vT, g_vT);
    cudaGetSymbolAddress((void**)&Ehi, g_Ehi);   cudaGetSymbolAddress((void**)&Elo, g_Elo);
    cudaGetSymbolAddress((void**)&chi, g_chi);   cudaGetSymbolAddress((void**)&clo, g_clo);
    cudaGetSymbolAddress((void**)&psum, g_psum); cudaGetSymbolAddress((void**)&rcpd, g_rcpd);

    cudaFuncSetAttribute(gemm2_tc,     cudaFuncAttributeMaxDynamicSharedMemorySize, SMEM2);
    cudaFuncSetAttribute(gemm2_qkv,    cudaFuncAttributeMaxDynamicSharedMemorySize, SMEM2);
    cudaFuncSetAttribute(gemm2_scores, cudaFuncAttributeMaxDynamicSharedMemorySize, SMEM2);

    const int M = BB * SS;  // 8192
    dim3 blk(NTHREADS);

    // 0) conversions
    conv_split_h<<<(M * FF / 4 + 255) / 256, 256>>>(x, xhi, xlo, (long long)M * FF / 4);
    WconvP wp;
    wp.in[0] = Wq; wp.out[0] = wq;
    wp.in[1] = Wk; wp.out[1] = wk;
    wp.in[2] = Wv; wp.out[2] = wv;
    wp.in[3] = Wo; wp.out[3] = wo;
    conv_w4<<<dim3((DKK * FF / 4 + 255) / 256, 4), 256>>>(wp, (long long)DKK * FF / 4);

    // 1) fused QKV -> q,v fp16 hi/lo; k fp16 single (+bias)
    QKVP p;
    p.W[0] = wq; p.bias[0] = bq; p.Oh[0] = qhi; p.Ol[0] = qlo;
    p.W[1] = wk; p.bias[1] = bk; p.Oh[1] = ks;  p.Ol[1] = nullptr;
    p.W[2] = wv; p.bias[2] = bv; p.Oh[2] = vhi; p.Ol[2] = vlo;
    dim3 g1(DKK / 128, M / 128, 3);
    gemm2_qkv<<<g1, blk, SMEM2>>>(xhi, xlo, p, FF, FF, FF, DKK);

    // 2) scores (fp16 2-term) + fused exp -> E fp16 hi/lo + col psums
    dim3 g2(SS / 128, SS / 128, BB);
    gemm2_scores<<<g2, blk, SMEM2>>>(qhi, qlo, ks, Ehi, Elo, psum, 1.0f / 32.0f);

    // 3) rcpd = 1/colsum
    reduce_rcpd<<<BB * SS / 256, 256>>>(psum, rcpd);

    // 4) transpose v -> vT (fp16 single) with rcp folded
    dim3 g4(DKK / 32, SS / 32, BB);
    transpose_scale<<<g4, dim3(32, 8)>>>(vhi, vlo, rcpd, vT, SS, DKK);

    // 5) ctx = E @ V' (fp16 2-term) -> ctx fp16 hi/lo
    dim3 g5(DKK / 128, SS / 128, BB);
    gemm2_tc<<<g5, blk, SMEM2>>>(Ehi, Elo, vT, nullptr, chi, clo, nullptr,
                                 SS, SS, SS, DKK,
                                 (long long)SS * SS, (long long)DKK * SS,
                                 (long long)SS * DKK);

    // 6) out = ctx @ Wo^T + bo (fp16 2-term) -> fp32
    dim3 g6(FF / 128, M / 128, 1);
    gemm2_tc<<<g6, blk, SMEM2>>>(chi, clo, wo, (float*)d_out, nullptr, nullptr,
                                 bo, DKK, DKK, DKK, FF, 0, 0, 0);
}

// round 14
// speedup vs baseline: 1.7243x; 1.1947x over previous
#include <cuda_runtime.h>
#include <cuda_fp16.h>
#include <cstdint>

#define BB 4
#define SS 2048
#define FF 1024
#define DKK 1024

// ---------------- scratch (device globals; no allocs allowed) ----------------
__device__ __half  g_xhi[BB*SS*FF],  g_xlo[BB*SS*FF];      // x fp16 split
__device__ __half  g_Wq[DKK*FF], g_Wk[DKK*FF], g_Wv[DKK*FF], g_Wo[FF*DKK];
__device__ __half  g_qhi[BB*SS*DKK], g_qlo[BB*SS*DKK];     // q fp16 split
__device__ __half  g_ks[BB*SS*DKK];                        // k fp16 single
__device__ __half  g_vs[BB*SS*DKK];                        // v fp16 single
__device__ __half  g_vT[BB*DKK*SS];                        // vT*rcp fp16 single
__device__ float   g_psum[(size_t)BB*16*SS];
__device__ float   g_rcpd[BB*SS];
__device__ __half  g_E[(size_t)BB*SS*SS];                  // E fp16 single
__device__ __half  g_ctx[BB*SS*DKK];                       // ctx fp16 single

// ---------------- PTX helpers ----------------
__device__ __forceinline__ uint32_t smem_to_u32(const void* p) {
    uint32_t a;
    asm("{ .reg .u64 t; cvta.to.shared.u64 t, %1; cvt.u32.u64 %0, t; }" : "=r"(a) : "l"(p));
    return a;
}
__device__ __forceinline__ void cp16(uint32_t dst, const void* src) {
    asm volatile("cp.async.cg.shared.global [%0], [%1], 16;" :: "r"(dst), "l"(src));
}
#define CP_COMMIT() asm volatile("cp.async.commit_group;" ::: "memory")
template <int N> __device__ __forceinline__ void cp_wait() {
    asm volatile("cp.async.wait_group %0;" :: "n"(N) : "memory");
}
__device__ __forceinline__ void ldmx4(uint32_t* r, uint32_t addr) {
    asm volatile("ldmatrix.sync.aligned.m8n8.x4.shared.b16 {%0,%1,%2,%3}, [%4];"
        : "=r"(r[0]), "=r"(r[1]), "=r"(r[2]), "=r"(r[3]) : "r"(addr));
}
__device__ __forceinline__ void mma_f16(float* c, const uint32_t* a, const uint32_t* b) {
    asm volatile(
        "mma.sync.aligned.m16n8k16.row.col.f32.f16.f16.f32 "
        "{%0,%1,%2,%3}, {%4,%5,%6,%7}, {%8,%9}, {%0,%1,%2,%3};"
        : "+f"(c[0]), "+f"(c[1]), "+f"(c[2]), "+f"(c[3])
        : "r"(a[0]), "r"(a[1]), "r"(a[2]), "r"(a[3]), "r"(b[0]), "r"(b[1]));
}

// smem: rows of 32 elems (64B) @ stride 80B (conflict-free ldmatrix)
#define BK     32
#define STRB   80
#define PLANE  (128 * STRB)            // 10240 B
#define SMEM3  (2 * 3 * PLANE)         // split-A: 3 planes x 2 stages = 61440
#define SMEM2  (2 * 2 * PLANE)         // single-A: 2 planes x 2 stages = 40960

#define NTHREADS 256

// ---------------------------------------------------------------------------
// Core: NT GEMM via fp16 mma.sync.
// SPLIT=1: A = A0+A1 (two planes, 2 sweeps). SPLIT=0: A = A0 (1 sweep).
// EXP=1: epilogue writes E=exp(alpha*acc) fp16 single + column psums.
// EXP=0: writes Cf (fp32 + bias) and/or Hh (fp16 single) and/or Hh+Hl pair.
// 8 warps (4x2), warp tile 32x64, CTA tile 128x128, BK=32, 2-stage pipeline.
// ---------------------------------------------------------------------------
template <int EXP, int SPLIT>
__device__ __forceinline__ void gemm_core(
    const __half* __restrict__ A0, const __half* __restrict__ A1,
    const __half* __restrict__ B,
    float* __restrict__ Cf, __half* __restrict__ Hh, __half* __restrict__ Hl,
    const float* __restrict__ bias, float* __restrict__ psum, float alpha,
    int K, int lda, int ldb, int ldc, size_t bm, size_t bn)
{
    constexpr uint32_t NPL = 2 + SPLIT;        // planes per stage
    constexpr uint32_t BUF = NPL * PLANE;
    constexpr uint32_t PB  = (1 + SPLIT) * PLANE;  // B plane offset

    extern __shared__ char smem[];
    uint32_t sbase = smem_to_u32(smem);
    int tid = threadIdx.x;
    int lane = tid & 31;
    int warp = tid >> 5;
    int m0w = (warp >> 1) * 32;
    int n0w = (warp & 1) * 64;

    float acc[2][8][4];
#pragma unroll
    for (int i = 0; i < 2; i++)
#pragma unroll
        for (int j = 0; j < 8; j++)
#pragma unroll
            for (int t = 0; t < 4; t++) acc[i][j][t] = 0.0f;

    int nch = K >> 5;

    auto prefetch = [&](int c) {
        int k0 = c << 5;
        uint32_t sb = sbase + (uint32_t)(c & 1) * BUF;
#pragma unroll
        for (int it = 0; it < 2; it++) {
            int id = tid + it * NTHREADS;
            int row = id >> 2;
            int seg = id & 3;
            uint32_t doff = (uint32_t)(row * STRB + seg * 16);
            size_t ea = (size_t)row * lda + k0 + seg * 8;
            size_t eb = (size_t)row * ldb + k0 + seg * 8;
            cp16(sb + 0 * PLANE + doff, A0 + ea);
            if (SPLIT) cp16(sb + 1 * PLANE + doff, A1 + ea);
            cp16(sb + PB + doff, B + eb);
        }
    };

    int aRow = m0w + (lane & 15);
    uint32_t aColB = (uint32_t)((lane >> 4) * 16);
    int bRow = n0w + ((lane >> 4) << 3) + (lane & 7);
    uint32_t bColB = (uint32_t)(((lane >> 3) & 1) * 16);

    prefetch(0); CP_COMMIT();

    for (int c = 0; c < nch; c++) {
        cp_wait<0>();
        __syncthreads();
        if (c + 1 < nch) { prefetch(c + 1); CP_COMMIT(); }

        uint32_t sb = sbase + (uint32_t)(c & 1) * BUF;
#pragma unroll
        for (int ks = 0; ks < 2; ks++) {
            uint32_t kB = (uint32_t)(ks * 32);
            uint32_t a_hi[2][4], a_lo[2][4];
#pragma unroll
            for (int mf = 0; mf < 2; mf++) {
                uint32_t off = (uint32_t)((aRow + mf * 16) * STRB) + kB + aColB;
                ldmx4(a_hi[mf], sb + 0 * PLANE + off);
                if (SPLIT) ldmx4(a_lo[mf], sb + 1 * PLANE + off);
            }
            uint32_t b[16];
#pragma unroll
            for (int ng = 0; ng < 4; ng++)
                ldmx4(&b[ng * 4], sb + PB +
                      (uint32_t)((bRow + ng * 16) * STRB) + kB + bColB);
#pragma unroll
            for (int mf = 0; mf < 2; mf++)
#pragma unroll
                for (int nf = 0; nf < 8; nf++)
                    mma_f16(acc[mf][nf], a_hi[mf], &b[nf * 2]);
            if (SPLIT) {
#pragma unroll
                for (int mf = 0; mf < 2; mf++)
#pragma unroll
                    for (int nf = 0; nf < 8; nf++)
                        mma_f16(acc[mf][nf], a_lo[mf], &b[nf * 2]);
            }
        }
    }

    int gidr = lane >> 2;
    int tidq = lane & 3;

    if (EXP) {
        float cs[8][2];
#pragma unroll
        for (int nf = 0; nf < 8; nf++) { cs[nf][0] = 0.0f; cs[nf][1] = 0.0f; }
#pragma unroll
        for (int mf = 0; mf < 2; mf++) {
#pragma unroll
            for (int nf = 0; nf < 8; nf++) {
                size_t r0 = bm + m0w + mf * 16 + gidr;
                size_t r1 = r0 + 8;
                size_t col = bn + n0w + nf * 8 + tidq * 2;
                float e00 = __expf(acc[mf][nf][0] * alpha);
                float e01 = __expf(acc[mf][nf][1] * alpha);
                float e10 = __expf(acc[mf][nf][2] * alpha);
                float e11 = __expf(acc[mf][nf][3] * alpha);
                cs[nf][0] += e00 + e10;
                cs[nf][1] += e01 + e11;
                *(__half2*)(Hh + r0 * ldc + col) = __floats2half2_rn(e00, e01);
                *(__half2*)(Hh + r1 * ldc + col) = __floats2half2_rn(e10, e11);
            }
        }
#pragma unroll
        for (int nf = 0; nf < 8; nf++)
#pragma unroll
            for (int t = 0; t < 2; t++) {
                float v = cs[nf][t];
                v += __shfl_xor_sync(0xffffffff, v, 4);
                v += __shfl_xor_sync(0xffffffff, v, 8);
                v += __shfl_xor_sync(0xffffffff, v, 16);
                cs[nf][t] = v;
            }
        float* sred = (float*)smem;
        __syncthreads();
        if (gidr == 0) {
#pragma unroll
            for (int nf = 0; nf < 8; nf++) {
                sred[(warp >> 1) * 128 + n0w + nf * 8 + tidq * 2 + 0] = cs[nf][0];
                sred[(warp >> 1) * 128 + n0w + nf * 8 + tidq * 2 + 1] = cs[nf][1];
            }
        }
        __syncthreads();
        if (tid < 128)
            psum[tid] = sred[tid] + sred[128 + tid] + sred[256 + tid] + sred[384 + tid];
        return;
    }

#pragma unroll
    for (int mf = 0; mf < 2; mf++) {
#pragma unroll
        for (int nf = 0; nf < 8; nf++) {
            size_t r0 = bm + m0w + mf * 16 + gidr;
            size_t r1 = r0 + 8;
            size_t col = bn + n0w + nf * 8 + tidq * 2;
            float b0 = bias ? bias[col] : 0.0f;
            float b1 = bias ? bias[col + 1] : 0.0f;
            float c00 = acc[mf][nf][0] + b0;
            float c01 = acc[mf][nf][1] + b1;
            float c10 = acc[mf][nf][2] + b0;
            float c11 = acc[mf][nf][3] + b1;
            if (Cf) {
                *(float2*)(Cf + r0 * ldc + col) = make_float2(c00, c01);
                *(float2*)(Cf + r1 * ldc + col) = make_float2(c10, c11);
            }
            if (Hh) {
                __half2 h0 = __floats2half2_rn(c00, c01);
                __half2 h1 = __floats2half2_rn(c10, c11);
                *(__half2*)(Hh + r0 * ldc + col) = h0;
                *(__half2*)(Hh + r1 * ldc + col) = h1;
                if (Hl) {
                    __half2 l0 = __floats2half2_rn(
                        c00 - __half2float(__low2half(h0)),
                        c01 - __half2float(__high2half(h0)));
                    __half2 l1 = __floats2half2_rn(
                        c10 - __half2float(__low2half(h1)),
                        c11 - __half2float(__high2half(h1)));
                    *(__half2*)(Hl + r0 * ldc + col) = l0;
                    *(__half2*)(Hl + r1 * ldc + col) = l1;
                }
            }
        }
    }
}

// Single-A batched NT GEMM (1 sweep)
__global__ __launch_bounds__(NTHREADS, 2) void gemm1_tc(
    const __half* __restrict__ A, const __half* __restrict__ B,
    float* __restrict__ Cf, __half* __restrict__ Hh,
    const float* __restrict__ bias,
    int K, int lda, int ldb, int ldc,
    long long sA, long long sB, long long sC)
{
    int bz = blockIdx.z;
    size_t bm = (size_t)blockIdx.y * 128;
    size_t bn = (size_t)blockIdx.x * 128;
    gemm_core<0, 0>(A + (size_t)bz * sA + bm * lda, nullptr,
                    B + (size_t)bz * sB + bn * ldb,
                    Cf ? Cf + (size_t)bz * sC : nullptr,
                    Hh ? Hh + (size_t)bz * sC : nullptr, nullptr,
                    bias, nullptr, 0.0f, K, lda, ldb, ldc, bm, bn);
}

// Scores: split-A, fused exp epilogue, E single fp16
__global__ __launch_bounds__(NTHREADS, 2) void gemm2_scores(
    const __half* __restrict__ Qhi, const __half* __restrict__ Qlo,
    const __half* __restrict__ Ks, __half* __restrict__ E,
    float* __restrict__ psum_all, float alpha)
{
    int bz = blockIdx.z;
    size_t bm = (size_t)blockIdx.y * 128;
    size_t bn = (size_t)blockIdx.x * 128;
    float* ps = psum_all + ((size_t)bz * gridDim.y + blockIdx.y) * SS + bn;
    gemm_core<1, 1>(Qhi + (size_t)bz * SS * DKK + bm * DKK,
                    Qlo + (size_t)bz * SS * DKK + bm * DKK,
                    Ks + (size_t)bz * SS * DKK + bn * DKK,
                    nullptr, E + (size_t)bz * SS * SS, nullptr,
                    nullptr, ps, alpha, DKK, DKK, DKK, SS, bm, bn);
}

// Fused QKV: split-A; q = fp16 pair, k = single, v = single
struct QKVP {
    const __half* W[3];
    const float* bias[3];
    __half* Oh[3];
    __half* Ol[3];   // null -> single-precision store
};
__global__ __launch_bounds__(NTHREADS, 2) void gemm2_qkv(
    const __half* __restrict__ Ahi, const __half* __restrict__ Alo,
    QKVP p, int K, int lda, int ldb, int ldc)
{
    int z = blockIdx.z;
    size_t bm = (size_t)blockIdx.y * 128;
    size_t bn = (size_t)blockIdx.x * 128;
    gemm_core<0, 1>(Ahi + bm * lda, Alo + bm * lda, p.W[z] + bn * ldb,
                    nullptr, p.Oh[z], p.Ol[z],
                    p.bias[z], nullptr, 0.0f, K, lda, ldb, ldc, bm, bn);
}

// ---------------------------------------------------------------------------
__global__ __launch_bounds__(256) void conv_split_h(
    const float* __restrict__ in, __half* __restrict__ hi,
    __half* __restrict__ lo, long long n4)
{
    long long i = (long long)blockIdx.x * blockDim.x + threadIdx.x;
    if (i >= n4) return;
    float4 v = ((const float4*)in)[i];
    __half2 h0 = __floats2half2_rn(v.x, v.y);
    __half2 h1 = __floats2half2_rn(v.z, v.w);
    float r0 = v.x - __half2float(__low2half(h0));
    float r1 = v.y - __half2float(__high2half(h0));
    float r2 = v.z - __half2float(__low2half(h1));
    float r3 = v.w - __half2float(__high2half(h1));
    ((__half2*)hi)[2 * i] = h0;
    ((__half2*)hi)[2 * i + 1] = h1;
    ((__half2*)lo)[2 * i] = __floats2half2_rn(r0, r1);
    ((__half2*)lo)[2 * i + 1] = __floats2half2_rn(r2, r3);
}

struct WconvP {
    const float* in[4];
    __half* out[4];
};
__global__ __launch_bounds__(256) void conv_w4(WconvP p, long long n4)
{
    int w = blockIdx.y;
    long long i = (long long)blockIdx.x * blockDim.x + threadIdx.x;
    if (i >= n4) return;
    float4 v = ((const float4*)p.in[w])[i];
    ((__half2*)p.out[w])[2 * i] = __floats2half2_rn(v.x, v.y);
    ((__half2*)p.out[w])[2 * i + 1] = __floats2half2_rn(v.z, v.w);
}

__global__ __launch_bounds__(256) void reduce_rcpd(
    const float* __restrict__ psum, float* __restrict__ rcpd)
{
    int i = blockIdx.x * blockDim.x + threadIdx.x;
    int b = i >> 11;
    int col = i & (SS - 1);
    const float* p = psum + (size_t)b * 16 * SS + col;
    float s = 0.0f;
#pragma unroll
    for (int t = 0; t < 16; t++) s += p[(size_t)t * SS];
    rcpd[i] = 1.0f / s;
}

// transpose + scale: vT[d][k] = v[k][d] * rcp[k], fp16 single
__global__ __launch_bounds__(256) void transpose_scale(
    const __half* __restrict__ iv, const float* __restrict__ rcpd,
    __half* __restrict__ oT, int rows, int cols)
{
    __shared__ __half t0[32][33];
    int z = blockIdx.z;
    size_t ioff = (size_t)z * rows * cols;
    int c0 = blockIdx.x * 32, r0 = blockIdx.y * 32;
    int tx = threadIdx.x, ty = threadIdx.y;

#pragma unroll
    for (int j = 0; j < 32; j += 8) {
        int r = r0 + ty + j;
        float rcp = rcpd[(size_t)z * rows + r];
        size_t idx = ioff + (size_t)r * cols + c0 + tx;
        t0[ty + j][tx] = __float2half(__half2float(iv[idx]) * rcp);
    }
    __syncthreads();
#pragma unroll
    for (int j = 0; j < 32; j += 8) {
        size_t odx = ioff + (size_t)(c0 + ty + j) * rows + r0 + tx;
        oT[odx] = t0[tx][ty + j];
    }
}

// ---------------------------------------------------------------------------
extern "C" void kernel_launch(void* const* d_in, const int* in_sizes, int n_in,
                              void* d_out, int out_size)
{
    const float* x  = (const float*)d_in[0];
    const float* Wq = (const float*)d_in[1];
    const float* bq = (const float*)d_in[2];
    const float* Wk = (const float*)d_in[3];
    const float* bk = (const float*)d_in[4];
    const float* Wv = (const float*)d_in[5];
    const float* bv = (const float*)d_in[6];
    const float* Wo = (const float*)d_in[7];
    const float* bo = (const float*)d_in[8];

    __half *xhi, *xlo, *wq, *wk, *wv, *wo, *qhi, *qlo, *ks, *vs, *vT, *E, *ctx;
    float *psum, *rcpd;
    cudaGetSymbolAddress((void**)&xhi, g_xhi);   cudaGetSymbolAddress((void**)&xlo, g_xlo);
    cudaGetSymbolAddress((void**)&wq, g_Wq);     cudaGetSymbolAddress((void**)&wk, g_Wk);
    cudaGetSymbolAddress((void**)&wv, g_Wv);     cudaGetSymbolAddress((void**)&wo, g_Wo);
    cudaGetSymbolAddress((void**)&qhi, g_qhi);   cudaGetSymbolAddress((void**)&qlo, g_qlo);
    cudaGetSymbolAddress((void**)&ks, g_ks);     cudaGetSymbolAddress((void**)&vs, g_vs);
    cudaGetSymbolAddress((void**)&vT, g_vT);     cudaGetSymbolAddress((void**)&E, g_E);
    cudaGetSymbolAddress((void**)&ctx, g_ctx);
    cudaGetSymbolAddress((void**)&psum, g_psum); cudaGetSymbolAddress((void**)&rcpd, g_rcpd);

    cudaFuncSetAttribute(gemm1_tc,     cudaFuncAttributeMaxDynamicSharedMemorySize, SMEM2);
    cudaFuncSetAttribute(gemm2_qkv,    cudaFuncAttributeMaxDynamicSharedMemorySize, SMEM3);
    cudaFuncSetAttribute(gemm2_scores, cudaFuncAttributeMaxDynamicSharedMemorySize, SMEM3);

    const int M = BB * SS;  // 8192
    dim3 blk(NTHREADS);

    // 0) conversions
    conv_split_h<<<(M * FF / 4 + 255) / 256, 256>>>(x, xhi, xlo, (long long)M * FF / 4);
    WconvP wp;
    wp.in[0] = Wq; wp.out[0] = wq;
    wp.in[1] = Wk; wp.out[1] = wk;
    wp.in[2] = Wv; wp.out[2] = wv;
    wp.in[3] = Wo; wp.out[3] = wo;
    conv_w4<<<dim3((DKK * FF / 4 + 255) / 256, 4), 256>>>(wp, (long long)DKK * FF / 4);

    // 1) fused QKV -> q fp16 hi/lo; k,v fp16 single (+bias)
    QKVP p;
    p.W[0] = wq; p.bias[0] = bq; p.Oh[0] = qhi; p.Ol[0] = qlo;
    p.W[1] = wk; p.bias[1] = bk; p.Oh[1] = ks;  p.Ol[1] = nullptr;
    p.W[2] = wv; p.bias[2] = bv; p.Oh[2] = vs;  p.Ol[2] = nullptr;
    dim3 g1(DKK / 128, M / 128, 3);
    gemm2_qkv<<<g1, blk, SMEM3>>>(xhi, xlo, p, FF, FF, FF, DKK);

    // 2) scores (q split x k single) + fused exp -> E fp16 single + psums
    dim3 g2(SS / 128, SS / 128, BB);
    gemm2_scores<<<g2, blk, SMEM3>>>(qhi, qlo, ks, E, psum, 1.0f / 32.0f);

    // 3) rcpd = 1/colsum
    reduce_rcpd<<<BB * SS / 256, 256>>>(psum, rcpd);

    // 4) transpose v -> vT with rcp folded (fp16 single)
    dim3 g4(DKK / 32, SS / 32, BB);
    transpose_scale<<<g4, dim3(32, 8)>>>(vs, rcpd, vT, SS, DKK);

    // 5) ctx = E @ V' (single x single, 1 sweep) -> ctx fp16 single
    dim3 g5(DKK / 128, SS / 128, BB);
    gemm1_tc<<<g5, blk, SMEM2>>>(E, vT, nullptr, ctx, nullptr,
                                 SS, SS, SS, DKK,
                                 (long long)SS * SS, (long long)DKK * SS,
                                 (long long)SS * DKK);

    // 6) out = ctx @ Wo^T + bo (single x single, 1 sweep) -> fp32
    dim3 g6(FF / 128, M / 128, 1);
    gemm1_tc<<<g6, blk, SMEM2>>>(ctx, wo, (float*)d_out, nullptr, bo,
                                 DKK, DKK, DKK, FF, 0, 0, 0);
}

// round 15
// speedup vs baseline: 1.9654x; 1.1398x over previous
#include <cuda_runtime.h>
#include <cuda_fp16.h>
#include <cstdint>

#define BB 4
#define SS 2048
#define FF 1024
#define DKK 1024

// ---------------- scratch (device globals; no allocs allowed) ----------------
__device__ __half  g_x[BB*SS*FF];                          // x fp16
__device__ __half  g_Wq[DKK*FF], g_Wk[DKK*FF], g_Wv[DKK*FF], g_Wo[FF*DKK];
__device__ __half  g_q[BB*SS*DKK];                         // q fp16
__device__ __half  g_k[BB*SS*DKK];                         // k fp16
__device__ __half  g_v[BB*SS*DKK];                         // v fp16
__device__ __half  g_vT[BB*DKK*SS];                        // vT*rcp fp16
__device__ float   g_psum[(size_t)BB*16*SS];
__device__ float   g_rcpd[BB*SS];
__device__ __half  g_E[(size_t)BB*SS*SS];                  // E fp16
__device__ __half  g_ctx[BB*SS*DKK];                       // ctx fp16

// ---------------- PTX helpers ----------------
__device__ __forceinline__ uint32_t smem_to_u32(const void* p) {
    uint32_t a;
    asm("{ .reg .u64 t; cvta.to.shared.u64 t, %1; cvt.u32.u64 %0, t; }" : "=r"(a) : "l"(p));
    return a;
}
__device__ __forceinline__ void cp16(uint32_t dst, const void* src) {
    asm volatile("cp.async.cg.shared.global [%0], [%1], 16;" :: "r"(dst), "l"(src));
}
#define CP_COMMIT() asm volatile("cp.async.commit_group;" ::: "memory")
template <int N> __device__ __forceinline__ void cp_wait() {
    asm volatile("cp.async.wait_group %0;" :: "n"(N) : "memory");
}
__device__ __forceinline__ void ldmx4(uint32_t* r, uint32_t addr) {
    asm volatile("ldmatrix.sync.aligned.m8n8.x4.shared.b16 {%0,%1,%2,%3}, [%4];"
        : "=r"(r[0]), "=r"(r[1]), "=r"(r[2]), "=r"(r[3]) : "r"(addr));
}
__device__ __forceinline__ void mma_f16(float* c, const uint32_t* a, const uint32_t* b) {
    asm volatile(
        "mma.sync.aligned.m16n8k16.row.col.f32.f16.f16.f32 "
        "{%0,%1,%2,%3}, {%4,%5,%6,%7}, {%8,%9}, {%0,%1,%2,%3};"
        : "+f"(c[0]), "+f"(c[1]), "+f"(c[2]), "+f"(c[3])
        : "r"(a[0]), "r"(a[1]), "r"(a[2]), "r"(a[3]), "r"(b[0]), "r"(b[1]));
}

// smem: rows of 32 elems (64B) @ stride 80B (conflict-free ldmatrix)
#define BK     32
#define STRB   80
#define PLANE  (128 * STRB)            // 10240 B
#define BUF    (2 * PLANE)             // A + B planes
#define SMEM_T (2 * BUF)               // 40960 -> 2+ CTAs/SM

#define NTHREADS 256

// ---------------------------------------------------------------------------
// Core: NT GEMM via fp16 mma.sync, single-precision operands, 1 sweep.
// EXP=1: epilogue writes E=exp(alpha*acc) fp16 + per-tile column psums.
// EXP=0: writes Cf (fp32 + bias) and/or Hh (fp16, + bias).
// 8 warps (4x2), warp tile 32x64, CTA tile 128x128, BK=32, 2-stage pipeline.
// ---------------------------------------------------------------------------
template <int EXP>
__device__ __forceinline__ void gemm_core(
    const __half* __restrict__ A, const __half* __restrict__ B,
    float* __restrict__ Cf, __half* __restrict__ Hh,
    const float* __restrict__ bias, float* __restrict__ psum, float alpha,
    int K, int lda, int ldb, int ldc, size_t bm, size_t bn)
{
    extern __shared__ char smem[];
    uint32_t sbase = smem_to_u32(smem);
    int tid = threadIdx.x;
    int lane = tid & 31;
    int warp = tid >> 5;
    int m0w = (warp >> 1) * 32;
    int n0w = (warp & 1) * 64;

    float acc[2][8][4];
#pragma unroll
    for (int i = 0; i < 2; i++)
#pragma unroll
        for (int j = 0; j < 8; j++)
#pragma unroll
            for (int t = 0; t < 4; t++) acc[i][j][t] = 0.0f;

    int nch = K >> 5;

    auto prefetch = [&](int c) {
        int k0 = c << 5;
        uint32_t sb = sbase + (uint32_t)(c & 1) * BUF;
#pragma unroll
        for (int it = 0; it < 2; it++) {
            int id = tid + it * NTHREADS;
            int row = id >> 2;
            int seg = id & 3;
            uint32_t doff = (uint32_t)(row * STRB + seg * 16);
            cp16(sb + 0 * PLANE + doff, A + (size_t)row * lda + k0 + seg * 8);
            cp16(sb + 1 * PLANE + doff, B + (size_t)row * ldb + k0 + seg * 8);
        }
    };

    int aRow = m0w + (lane & 15);
    uint32_t aColB = (uint32_t)((lane >> 4) * 16);
    int bRow = n0w + ((lane >> 4) << 3) + (lane & 7);
    uint32_t bColB = (uint32_t)(((lane >> 3) & 1) * 16);

    prefetch(0); CP_COMMIT();

    for (int c = 0; c < nch; c++) {
        cp_wait<0>();
        __syncthreads();
        if (c + 1 < nch) { prefetch(c + 1); CP_COMMIT(); }

        uint32_t sb = sbase + (uint32_t)(c & 1) * BUF;
#pragma unroll
        for (int ks = 0; ks < 2; ks++) {
            uint32_t kB = (uint32_t)(ks * 32);
            uint32_t a[2][4];
#pragma unroll
            for (int mf = 0; mf < 2; mf++)
                ldmx4(a[mf], sb + 0 * PLANE +
                      (uint32_t)((aRow + mf * 16) * STRB) + kB + aColB);
            uint32_t b[16];
#pragma unroll
            for (int ng = 0; ng < 4; ng++)
                ldmx4(&b[ng * 4], sb + 1 * PLANE +
                      (uint32_t)((bRow + ng * 16) * STRB) + kB + bColB);
#pragma unroll
            for (int mf = 0; mf < 2; mf++)
#pragma unroll
                for (int nf = 0; nf < 8; nf++)
                    mma_f16(acc[mf][nf], a[mf], &b[nf * 2]);
        }
    }

    int gidr = lane >> 2;
    int tidq = lane & 3;

    if (EXP) {
        float cs[8][2];
#pragma unroll
        for (int nf = 0; nf < 8; nf++) { cs[nf][0] = 0.0f; cs[nf][1] = 0.0f; }
#pragma unroll
        for (int mf = 0; mf < 2; mf++) {
#pragma unroll
            for (int nf = 0; nf < 8; nf++) {
                size_t r0 = bm + m0w + mf * 16 + gidr;
                size_t r1 = r0 + 8;
                size_t col = bn + n0w + nf * 8 + tidq * 2;
                float e00 = __expf(acc[mf][nf][0] * alpha);
                float e01 = __expf(acc[mf][nf][1] * alpha);
                float e10 = __expf(acc[mf][nf][2] * alpha);
                float e11 = __expf(acc[mf][nf][3] * alpha);
                cs[nf][0] += e00 + e10;
                cs[nf][1] += e01 + e11;
                *(__half2*)(Hh + r0 * ldc + col) = __floats2half2_rn(e00, e01);
                *(__half2*)(Hh + r1 * ldc + col) = __floats2half2_rn(e10, e11);
            }
        }
#pragma unroll
        for (int nf = 0; nf < 8; nf++)
#pragma unroll
            for (int t = 0; t < 2; t++) {
                float v = cs[nf][t];
                v += __shfl_xor_sync(0xffffffff, v, 4);
                v += __shfl_xor_sync(0xffffffff, v, 8);
                v += __shfl_xor_sync(0xffffffff, v, 16);
                cs[nf][t] = v;
            }
        float* sred = (float*)smem;
        __syncthreads();
        if (gidr == 0) {
#pragma unroll
            for (int nf = 0; nf < 8; nf++) {
                sred[(warp >> 1) * 128 + n0w + nf * 8 + tidq * 2 + 0] = cs[nf][0];
                sred[(warp >> 1) * 128 + n0w + nf * 8 + tidq * 2 + 1] = cs[nf][1];
            }
        }
        __syncthreads();
        if (tid < 128)
            psum[tid] = sred[tid] + sred[128 + tid] + sred[256 + tid] + sred[384 + tid];
        return;
    }

#pragma unroll
    for (int mf = 0; mf < 2; mf++) {
#pragma unroll
        for (int nf = 0; nf < 8; nf++) {
            size_t r0 = bm + m0w + mf * 16 + gidr;
            size_t r1 = r0 + 8;
            size_t col = bn + n0w + nf * 8 + tidq * 2;
            float b0 = bias ? bias[col] : 0.0f;
            float b1 = bias ? bias[col + 1] : 0.0f;
            float c00 = acc[mf][nf][0] + b0;
            float c01 = acc[mf][nf][1] + b1;
            float c10 = acc[mf][nf][2] + b0;
            float c11 = acc[mf][nf][3] + b1;
            if (Cf) {
                *(float2*)(Cf + r0 * ldc + col) = make_float2(c00, c01);
                *(float2*)(Cf + r1 * ldc + col) = make_float2(c10, c11);
            }
            if (Hh) {
                *(__half2*)(Hh + r0 * ldc + col) = __floats2half2_rn(c00, c01);
                *(__half2*)(Hh + r1 * ldc + col) = __floats2half2_rn(c10, c11);
            }
        }
    }
}

// Generic batched single-fp16 NT GEMM (1 sweep)
__global__ __launch_bounds__(NTHREADS, 2) void gemm1_tc(
    const __half* __restrict__ A, const __half* __restrict__ B,
    float* __restrict__ Cf, __half* __restrict__ Hh,
    const float* __restrict__ bias,
    int K, int lda, int ldb, int ldc,
    long long sA, long long sB, long long sC)
{
    int bz = blockIdx.z;
    size_t bm = (size_t)blockIdx.y * 128;
    size_t bn = (size_t)blockIdx.x * 128;
    gemm_core<0>(A + (size_t)bz * sA + bm * lda,
                 B + (size_t)bz * sB + bn * ldb,
                 Cf ? Cf + (size_t)bz * sC : nullptr,
                 Hh ? Hh + (size_t)bz * sC : nullptr,
                 bias, nullptr, 0.0f, K, lda, ldb, ldc, bm, bn);
}

// Scores: single x single, fused exp epilogue
__global__ __launch_bounds__(NTHREADS, 2) void gemm1_scores(
    const __half* __restrict__ Q, const __half* __restrict__ Ks,
    __half* __restrict__ E, float* __restrict__ psum_all, float alpha)
{
    int bz = blockIdx.z;
    size_t bm = (size_t)blockIdx.y * 128;
    size_t bn = (size_t)blockIdx.x * 128;
    float* ps = psum_all + ((size_t)bz * gridDim.y + blockIdx.y) * SS + bn;
    gemm_core<1>(Q + (size_t)bz * SS * DKK + bm * DKK,
                 Ks + (size_t)bz * SS * DKK + bn * DKK,
                 nullptr, E + (size_t)bz * SS * SS,
                 nullptr, ps, alpha, DKK, DKK, DKK, SS, bm, bn);
}

// Fused QKV: z selects weight/bias/output (all single fp16)
struct QKVP {
    const __half* W[3];
    const float* bias[3];
    __half* O[3];
};
__global__ __launch_bounds__(NTHREADS, 2) void gemm1_qkv(
    const __half* __restrict__ X, QKVP p, int K, int lda, int ldb, int ldc)
{
    int z = blockIdx.z;
    size_t bm = (size_t)blockIdx.y * 128;
    size_t bn = (size_t)blockIdx.x * 128;
    gemm_core<0>(X + bm * lda, p.W[z] + bn * ldb,
                 nullptr, p.O[z], p.bias[z], nullptr, 0.0f,
                 K, lda, ldb, ldc, bm, bn);
}

// ---------------------------------------------------------------------------
// fp32 -> fp16 conversions: x plus the 4 weights, one launch (z selects)
// ---------------------------------------------------------------------------
struct ConvP {
    const float* in[5];
    __half* out[5];
    long long n4[5];
};
__global__ __launch_bounds__(256) void conv_h5(ConvP p)
{
    int w = blockIdx.y;
    long long i = (long long)blockIdx.x * blockDim.x + threadIdx.x;
    if (i >= p.n4[w]) return;
    float4 v = ((const float4*)p.in[w])[i];
    ((__half2*)p.out[w])[2 * i] = __floats2half2_rn(v.x, v.y);
    ((__half2*)p.out[w])[2 * i + 1] = __floats2half2_rn(v.z, v.w);
}

__global__ __launch_bounds__(256) void reduce_rcpd(
    const float* __restrict__ psum, float* __restrict__ rcpd)
{
    int i = blockIdx.x * blockDim.x + threadIdx.x;
    int b = i >> 11;
    int col = i & (SS - 1);
    const float* p = psum + (size_t)b * 16 * SS + col;
    float s = 0.0f;
#pragma unroll
    for (int t = 0; t < 16; t++) s += p[(size_t)t * SS];
    rcpd[i] = 1.0f / s;
}

// transpose + scale: vT[d][k] = v[k][d] * rcp[k], fp16
__global__ __launch_bounds__(256) void transpose_scale(
    const __half* __restrict__ iv, const float* __restrict__ rcpd,
    __half* __restrict__ oT, int rows, int cols)
{
    __shared__ __half t0[32][33];
    int z = blockIdx.z;
    size_t ioff = (size_t)z * rows * cols;
    int c0 = blockIdx.x * 32, r0 = blockIdx.y * 32;
    int tx = threadIdx.x, ty = threadIdx.y;

#pragma unroll
    for (int j = 0; j < 32; j += 8) {
        int r = r0 + ty + j;
        float rcp = rcpd[(size_t)z * rows + r];
        size_t idx = ioff + (size_t)r * cols + c0 + tx;
        t0[ty + j][tx] = __float2half(__half2float(iv[idx]) * rcp);
    }
    __syncthreads();
#pragma unroll
    for (int j = 0; j < 32; j += 8) {
        size_t odx = ioff + (size_t)(c0 + ty + j) * rows + r0 + tx;
        oT[odx] = t0[tx][ty + j];
    }
}

// ---------------------------------------------------------------------------
extern "C" void kernel_launch(void* const* d_in, const int* in_sizes, int n_in,
                              void* d_out, int out_size)
{
    const float* x  = (const float*)d_in[0];
    const float* Wq = (const float*)d_in[1];
    const float* bq = (const float*)d_in[2];
    const float* Wk = (const float*)d_in[3];
    const float* bk = (const float*)d_in[4];
    const float* Wv = (const float*)d_in[5];
    const float* bv = (const float*)d_in[6];
    const float* Wo = (const float*)d_in[7];
    const float* bo = (const float*)d_in[8];

    __half *xh, *wq, *wk, *wv, *wo, *q, *k, *v, *vT, *E, *ctx;
    float *psum, *rcpd;
    cudaGetSymbolAddress((void**)&xh, g_x);
    cudaGetSymbolAddress((void**)&wq, g_Wq);  cudaGetSymbolAddress((void**)&wk, g_Wk);
    cudaGetSymbolAddress((void**)&wv, g_Wv);  cudaGetSymbolAddress((void**)&wo, g_Wo);
    cudaGetSymbolAddress((void**)&q, g_q);    cudaGetSymbolAddress((void**)&k, g_k);
    cudaGetSymbolAddress((void**)&v, g_v);    cudaGetSymbolAddress((void**)&vT, g_vT);
    cudaGetSymbolAddress((void**)&E, g_E);    cudaGetSymbolAddress((void**)&ctx, g_ctx);
    cudaGetSymbolAddress((void**)&psum, g_psum);
    cudaGetSymbolAddress((void**)&rcpd, g_rcpd);

    cudaFuncSetAttribute(gemm1_tc,     cudaFuncAttributeMaxDynamicSharedMemorySize, SMEM_T);
    cudaFuncSetAttribute(gemm1_qkv,    cudaFuncAttributeMaxDynamicSharedMemorySize, SMEM_T);
    cudaFuncSetAttribute(gemm1_scores, cudaFuncAttributeMaxDynamicSharedMemorySize, SMEM_T);

    const int M = BB * SS;  // 8192

    // 0) conversions: x + 4 weights, one launch
    ConvP cp;
    cp.in[0] = x;  cp.out[0] = xh; cp.n4[0] = (long long)M * FF / 4;
    cp.in[1] = Wq; cp.out[1] = wq; cp.n4[1] = (long long)DKK * FF / 4;
    cp.in[2] = Wk; cp.out[2] = wk; cp.n4[2] = (long long)DKK * FF / 4;
    cp.in[3] = Wv; cp.out[3] = wv; cp.n4[3] = (long long)DKK * FF / 4;
    cp.in[4] = Wo; cp.out[4] = wo; cp.n4[4] = (long long)FF * DKK / 4;
    conv_h5<<<dim3((M * FF / 4 + 255) / 256, 5), 256>>>(cp);

    dim3 blk(NTHREADS);

    // 1) fused QKV (single fp16, 1 sweep) -> q,k,v (+bias)
    QKVP p;
    p.W[0] = wq; p.bias[0] = bq; p.O[0] = q;
    p.W[1] = wk; p.bias[1] = bk; p.O[1] = k;
    p.W[2] = wv; p.bias[2] = bv; p.O[2] = v;
    dim3 g1(DKK / 128, M / 128, 3);
    gemm1_qkv<<<g1, blk, SMEM_T>>>(xh, p, FF, FF, FF, DKK);

    // 2) scores (1 sweep) + fused exp -> E fp16 + col psums
    dim3 g2(SS / 128, SS / 128, BB);
    gemm1_scores<<<g2, blk, SMEM_T>>>(q, k, E, psum, 1.0f / 32.0f);

    // 3) rcpd = 1/colsum
    reduce_rcpd<<<BB * SS / 256, 256>>>(psum, rcpd);

    // 4) transpose v -> vT with rcp folded
    dim3 g4(DKK / 32, SS / 32, BB);
    transpose_scale<<<g4, dim3(32, 8)>>>(v, rcpd, vT, SS, DKK);

    // 5) ctx = E @ V' (1 sweep) -> ctx fp16
    dim3 g5(DKK / 128, SS / 128, BB);
    gemm1_tc<<<g5, blk, SMEM_T>>>(E, vT, nullptr, ctx, nullptr,
                                  SS, SS, SS, DKK,
                                  (long long)SS * SS, (long long)DKK * SS,
                                  (long long)SS * DKK);

    // 6) out = ctx @ Wo^T + bo (1 sweep) -> fp32
    dim3 g6(FF / 128, M / 128, 1);
    gemm1_tc<<<g6, blk, SMEM_T>>>(ctx, wo, (float*)d_out, nullptr, bo,
                                  DKK, DKK, DKK, FF, 0, 0, 0);
}

// round 16
// speedup vs baseline: 2.0785x; 1.0576x over previous
#include <cuda_runtime.h>
#include <cuda_fp16.h>
#include <cstdint>

#define BB 4
#define SS 2048
#define FF 1024
#define DKK 1024

// ---------------- scratch (device globals; no allocs allowed) ----------------
__device__ __half  g_x[BB*SS*FF];                          // x fp16
__device__ __half  g_Wq[DKK*FF], g_Wk[DKK*FF], g_Wv[DKK*FF], g_Wo[FF*DKK];
__device__ __half  g_q[BB*SS*DKK];                         // q fp16
__device__ __half  g_k[BB*SS*DKK];                         // k fp16
__device__ __half  g_v[BB*SS*DKK];                         // v fp16
__device__ __half  g_vT[BB*DKK*SS];                        // vT*rcp fp16
__device__ float   g_psum[(size_t)BB*16*SS];
__device__ float   g_rcpd[BB*SS];
__device__ __half  g_E[(size_t)BB*SS*SS];                  // E fp16
__device__ __half  g_ctx[BB*SS*DKK];                       // ctx fp16

// ---------------- PTX helpers ----------------
__device__ __forceinline__ uint32_t smem_to_u32(const void* p) {
    uint32_t a;
    asm("{ .reg .u64 t; cvta.to.shared.u64 t, %1; cvt.u32.u64 %0, t; }" : "=r"(a) : "l"(p));
    return a;
}
__device__ __forceinline__ void cp16(uint32_t dst, const void* src) {
    asm volatile("cp.async.cg.shared.global [%0], [%1], 16;" :: "r"(dst), "l"(src));
}
#define CP_COMMIT() asm volatile("cp.async.commit_group;" ::: "memory")
template <int N> __device__ __forceinline__ void cp_wait() {
    asm volatile("cp.async.wait_group %0;" :: "n"(N) : "memory");
}
__device__ __forceinline__ void ldmx4(uint32_t* r, uint32_t addr) {
    asm volatile("ldmatrix.sync.aligned.m8n8.x4.shared.b16 {%0,%1,%2,%3}, [%4];"
        : "=r"(r[0]), "=r"(r[1]), "=r"(r[2]), "=r"(r[3]) : "r"(addr));
}
__device__ __forceinline__ void mma_f16(float* c, const uint32_t* a, const uint32_t* b) {
    asm volatile(
        "mma.sync.aligned.m16n8k16.row.col.f32.f16.f16.f32 "
        "{%0,%1,%2,%3}, {%4,%5,%6,%7}, {%8,%9}, {%0,%1,%2,%3};"
        : "+f"(c[0]), "+f"(c[1]), "+f"(c[2]), "+f"(c[3])
        : "r"(a[0]), "r"(a[1]), "r"(a[2]), "r"(a[3]), "r"(b[0]), "r"(b[1]));
}

// smem: rows of 32 elems (64B) @ stride 80B (conflict-free ldmatrix)
#define BK     32
#define STRB   80
#define PLANE  (128 * STRB)            // 10240 B
#define BUF    (2 * PLANE)             // A + B planes
#define SMEM_T (2 * BUF)               // 40960 B -> 2 CTAs/SM

#define GTHREADS 128                   // 4 warps per GEMM CTA

// ---------------------------------------------------------------------------
// Core: NT GEMM via fp16 mma.sync, single operands, 1 sweep.
// 4 warps (2x2 grid), warp tile 64x64, CTA tile 128x128, BK=32, 2-stage.
// 8 ldmx4 per 32 MMAs per warp -> LDS demand ~64 B/cyc/SM (under 128 cap).
// EXP=1: writes E=exp(alpha*acc) fp16 + per-tile column psums.
// EXP=0: writes Cf (fp32 + bias) and/or Hh (fp16, + bias).
// ---------------------------------------------------------------------------
template <int EXP>
__device__ __forceinline__ void gemm_core(
    const __half* __restrict__ A, const __half* __restrict__ B,
    float* __restrict__ Cf, __half* __restrict__ Hh,
    const float* __restrict__ bias, float* __restrict__ psum, float alpha,
    int K, int lda, int ldb, int ldc, size_t bm, size_t bn)
{
    extern __shared__ char smem[];
    uint32_t sbase = smem_to_u32(smem);
    int tid = threadIdx.x;
    int lane = tid & 31;
    int warp = tid >> 5;               // 0..3
    int m0w = (warp >> 1) * 64;        // 2x2 warp grid, tile 64(m) x 64(n)
    int n0w = (warp & 1) * 64;

    float acc[4][8][4];
#pragma unroll
    for (int i = 0; i < 4; i++)
#pragma unroll
        for (int j = 0; j < 8; j++)
#pragma unroll
            for (int t = 0; t < 4; t++) acc[i][j][t] = 0.0f;

    int nch = K >> 5;

    auto prefetch = [&](int c) {
        int k0 = c << 5;
        uint32_t sb = sbase + (uint32_t)(c & 1) * BUF;
#pragma unroll
        for (int it = 0; it < 4; it++) {
            int id = tid + it * GTHREADS;     // 0..511
            int row = id >> 2;                // 0..127
            int seg = id & 3;
            uint32_t doff = (uint32_t)(row * STRB + seg * 16);
            cp16(sb + 0 * PLANE + doff, A + (size_t)row * lda + k0 + seg * 8);
            cp16(sb + 1 * PLANE + doff, B + (size_t)row * ldb + k0 + seg * 8);
        }
    };

    int aRow = m0w + (lane & 15);
    uint32_t aColB = (uint32_t)((lane >> 4) * 16);
    int bRow = n0w + ((lane >> 4) << 3) + (lane & 7);
    uint32_t bColB = (uint32_t)(((lane >> 3) & 1) * 16);

    prefetch(0); CP_COMMIT();

    for (int c = 0; c < nch; c++) {
        cp_wait<0>();
        __syncthreads();
        if (c + 1 < nch) { prefetch(c + 1); CP_COMMIT(); }

        uint32_t sb = sbase + (uint32_t)(c & 1) * BUF;
#pragma unroll
        for (int ks = 0; ks < 2; ks++) {
            uint32_t kB = (uint32_t)(ks * 32);
            uint32_t a[4][4];
#pragma unroll
            for (int mf = 0; mf < 4; mf++)
                ldmx4(a[mf], sb + 0 * PLANE +
                      (uint32_t)((aRow + mf * 16) * STRB) + kB + aColB);
            uint32_t b[16];
#pragma unroll
            for (int ng = 0; ng < 4; ng++)
                ldmx4(&b[ng * 4], sb + 1 * PLANE +
                      (uint32_t)((bRow + ng * 16) * STRB) + kB + bColB);
            // 32 independent accumulators -> RAW-free MMA stream
#pragma unroll
            for (int mf = 0; mf < 4; mf++)
#pragma unroll
                for (int nf = 0; nf < 8; nf++)
                    mma_f16(acc[mf][nf], a[mf], &b[nf * 2]);
        }
    }

    int gidr = lane >> 2;
    int tidq = lane & 3;

    if (EXP) {
        float cs[8][2];
#pragma unroll
        for (int nf = 0; nf < 8; nf++) { cs[nf][0] = 0.0f; cs[nf][1] = 0.0f; }
#pragma unroll
        for (int mf = 0; mf < 4; mf++) {
#pragma unroll
            for (int nf = 0; nf < 8; nf++) {
                size_t r0 = bm + m0w + mf * 16 + gidr;
                size_t r1 = r0 + 8;
                size_t col = bn + n0w + nf * 8 + tidq * 2;
                float e00 = __expf(acc[mf][nf][0] * alpha);
                float e01 = __expf(acc[mf][nf][1] * alpha);
                float e10 = __expf(acc[mf][nf][2] * alpha);
                float e11 = __expf(acc[mf][nf][3] * alpha);
                cs[nf][0] += e00 + e10;
                cs[nf][1] += e01 + e11;
                *(__half2*)(Hh + r0 * ldc + col) = __floats2half2_rn(e00, e01);
                *(__half2*)(Hh + r1 * ldc + col) = __floats2half2_rn(e10, e11);
            }
        }
        // reduce across the 8 row-group lanes
#pragma unroll
        for (int nf = 0; nf < 8; nf++)
#pragma unroll
            for (int t = 0; t < 2; t++) {
                float v = cs[nf][t];
                v += __shfl_xor_sync(0xffffffff, v, 4);
                v += __shfl_xor_sync(0xffffffff, v, 8);
                v += __shfl_xor_sync(0xffffffff, v, 16);
                cs[nf][t] = v;
            }
        float* sred = (float*)smem;   // 256 floats, reuse pipeline smem
        __syncthreads();
        if (gidr == 0) {
#pragma unroll
            for (int nf = 0; nf < 8; nf++) {
                int cl = n0w + nf * 8 + tidq * 2;
                sred[(warp >> 1) * 128 + cl + 0] = cs[nf][0];
                sred[(warp >> 1) * 128 + cl + 1] = cs[nf][1];
            }
        }
        __syncthreads();
        psum[tid] = sred[tid] + sred[128 + tid];
        return;
    }

#pragma unroll
    for (int mf = 0; mf < 4; mf++) {
#pragma unroll
        for (int nf = 0; nf < 8; nf++) {
            size_t r0 = bm + m0w + mf * 16 + gidr;
            size_t r1 = r0 + 8;
            size_t col = bn + n0w + nf * 8 + tidq * 2;
            float b0 = bias ? bias[col] : 0.0f;
            float b1 = bias ? bias[col + 1] : 0.0f;
            float c00 = acc[mf][nf][0] + b0;
            float c01 = acc[mf][nf][1] + b1;
            float c10 = acc[mf][nf][2] + b0;
            float c11 = acc[mf][nf][3] + b1;
            if (Cf) {
                *(float2*)(Cf + r0 * ldc + col) = make_float2(c00, c01);
                *(float2*)(Cf + r1 * ldc + col) = make_float2(c10, c11);
            }
            if (Hh) {
                *(__half2*)(Hh + r0 * ldc + col) = __floats2half2_rn(c00, c01);
                *(__half2*)(Hh + r1 * ldc + col) = __floats2half2_rn(c10, c11);
            }
        }
    }
}

// Generic batched single-fp16 NT GEMM
__global__ __launch_bounds__(GTHREADS, 2) void gemm1_tc(
    const __half* __restrict__ A, const __half* __restrict__ B,
    float* __restrict__ Cf, __half* __restrict__ Hh,
    const float* __restrict__ bias,
    int K, int lda, int ldb, int ldc,
    long long sA, long long sB, long long sC)
{
    int bz = blockIdx.z;
    size_t bm = (size_t)blockIdx.y * 128;
    size_t bn = (size_t)blockIdx.x * 128;
    gemm_core<0>(A + (size_t)bz * sA + bm * lda,
                 B + (size_t)bz * sB + bn * ldb,
                 Cf ? Cf + (size_t)bz * sC : nullptr,
                 Hh ? Hh + (size_t)bz * sC : nullptr,
                 bias, nullptr, 0.0f, K, lda, ldb, ldc, bm, bn);
}

// Scores: fused exp epilogue
__global__ __launch_bounds__(GTHREADS, 2) void gemm1_scores(
    const __half* __restrict__ Q, const __half* __restrict__ Ks,
    __half* __restrict__ E, float* __restrict__ psum_all, float alpha)
{
    int bz = blockIdx.z;
    size_t bm = (size_t)blockIdx.y * 128;
    size_t bn = (size_t)blockIdx.x * 128;
    float* ps = psum_all + ((size_t)bz * gridDim.y + blockIdx.y) * SS + bn;
    gemm_core<1>(Q + (size_t)bz * SS * DKK + bm * DKK,
                 Ks + (size_t)bz * SS * DKK + bn * DKK,
                 nullptr, E + (size_t)bz * SS * SS,
                 nullptr, ps, alpha, DKK, DKK, DKK, SS, bm, bn);
}

// Fused QKV: z selects weight/bias/output
struct QKVP {
    const __half* W[3];
    const float* bias[3];
    __half* O[3];
};
__global__ __launch_bounds__(GTHREADS, 2) void gemm1_qkv(
    const __half* __restrict__ X, QKVP p, int K, int lda, int ldb, int ldc)
{
    int z = blockIdx.z;
    size_t bm = (size_t)blockIdx.y * 128;
    size_t bn = (size_t)blockIdx.x * 128;
    gemm_core<0>(X + bm * lda, p.W[z] + bn * ldb,
                 nullptr, p.O[z], p.bias[z], nullptr, 0.0f,
                 K, lda, ldb, ldc, bm, bn);
}

// ---------------------------------------------------------------------------
// fp32 -> fp16 conversions: x + 4 weights, one launch
// ---------------------------------------------------------------------------
struct ConvP {
    const float* in[5];
    __half* out[5];
    long long n4[5];
};
__global__ __launch_bounds__(256) void conv_h5(ConvP p)
{
    int w = blockIdx.y;
    long long i = (long long)blockIdx.x * blockDim.x + threadIdx.x;
    if (i >= p.n4[w]) return;
    float4 v = ((const float4*)p.in[w])[i];
    ((__half2*)p.out[w])[2 * i] = __floats2half2_rn(v.x, v.y);
    ((__half2*)p.out[w])[2 * i + 1] = __floats2half2_rn(v.z, v.w);
}

__global__ __launch_bounds__(256) void reduce_rcpd(
    const float* __restrict__ psum, float* __restrict__ rcpd)
{
    int i = blockIdx.x * blockDim.x + threadIdx.x;
    int b = i >> 11;
    int col = i & (SS - 1);
    const float* p = psum + (size_t)b * 16 * SS + col;
    float s = 0.0f;
#pragma unroll
    for (int t = 0; t < 16; t++) s += p[(size_t)t * SS];
    rcpd[i] = 1.0f / s;
}

// transpose + scale: vT[d][k] = v[k][d] * rcp[k], fp16
__global__ __launch_bounds__(256) void transpose_scale(
    const __half* __restrict__ iv, const float* __restrict__ rcpd,
    __half* __restrict__ oT, int rows, int cols)
{
    __shared__ __half t0[32][33];
    int z = blockIdx.z;
    size_t ioff = (size_t)z * rows * cols;
    int c0 = blockIdx.x * 32, r0 = blockIdx.y * 32;
    int tx = threadIdx.x, ty = threadIdx.y;

#pragma unroll
    for (int j = 0; j < 32; j += 8) {
        int r = r0 + ty + j;
        float rcp = rcpd[(size_t)z * rows + r];
        size_t idx = ioff + (size_t)r * cols + c0 + tx;
        t0[ty + j][tx] = __float2half(__half2float(iv[idx]) * rcp);
    }
    __syncthreads();
#pragma unroll
    for (int j = 0; j < 32; j += 8) {
        size_t odx = ioff + (size_t)(c0 + ty + j) * rows + r0 + tx;
        oT[odx] = t0[tx][ty + j];
    }
}

// ---------------------------------------------------------------------------
extern "C" void kernel_launch(void* const* d_in, const int* in_sizes, int n_in,
                              void* d_out, int out_size)
{
    const float* x  = (const float*)d_in[0];
    const float* Wq = (const float*)d_in[1];
    const float* bq = (const float*)d_in[2];
    const float* Wk = (const float*)d_in[3];
    const float* bk = (const float*)d_in[4];
    const float* Wv = (const float*)d_in[5];
    const float* bv = (const float*)d_in[6];
    const float* Wo = (const float*)d_in[7];
    const float* bo = (const float*)d_in[8];

    __half *xh, *wq, *wk, *wv, *wo, *q, *k, *v, *vT, *E, *ctx;
    float *psum, *rcpd;
    cudaGetSymbolAddress((void**)&xh, g_x);
    cudaGetSymbolAddress((void**)&wq, g_Wq);  cudaGetSymbolAddress((void**)&wk, g_Wk);
    cudaGetSymbolAddress((void**)&wv, g_Wv);  cudaGetSymbolAddress((void**)&wo, g_Wo);
    cudaGetSymbolAddress((void**)&q, g_q);    cudaGetSymbolAddress((void**)&k, g_k);
    cudaGetSymbolAddress((void**)&v, g_v);    cudaGetSymbolAddress((void**)&vT, g_vT);
    cudaGetSymbolAddress((void**)&E, g_E);    cudaGetSymbolAddress((void**)&ctx, g_ctx);
    cudaGetSymbolAddress((void**)&psum, g_psum);
    cudaGetSymbolAddress((void**)&rcpd, g_rcpd);

    cudaFuncSetAttribute(gemm1_tc,     cudaFuncAttributeMaxDynamicSharedMemorySize, SMEM_T);
    cudaFuncSetAttribute(gemm1_qkv,    cudaFuncAttributeMaxDynamicSharedMemorySize, SMEM_T);
    cudaFuncSetAttribute(gemm1_scores, cudaFuncAttributeMaxDynamicSharedMemorySize, SMEM_T);

    const int M = BB * SS;  // 8192

    // 0) conversions: x + 4 weights, one launch
    ConvP cp;
    cp.in[0] = x;  cp.out[0] = xh; cp.n4[0] = (long long)M * FF / 4;
    cp.in[1] = Wq; cp.out[1] = wq; cp.n4[1] = (long long)DKK * FF / 4;
    cp.in[2] = Wk; cp.out[2] = wk; cp.n4[2] = (long long)DKK * FF / 4;
    cp.in[3] = Wv; cp.out[3] = wv; cp.n4[3] = (long long)DKK * FF / 4;
    cp.in[4] = Wo; cp.out[4] = wo; cp.n4[4] = (long long)FF * DKK / 4;
    conv_h5<<<dim3((M * FF / 4 + 255) / 256, 5), 256>>>(cp);

    dim3 blk(GTHREADS);

    // 1) fused QKV (1 sweep) -> q,k,v (+bias)
    QKVP p;
    p.W[0] = wq; p.bias[0] = bq; p.O[0] = q;
    p.W[1] = wk; p.bias[1] = bk; p.O[1] = k;
    p.W[2] = wv; p.bias[2] = bv; p.O[2] = v;
    dim3 g1(DKK / 128, M / 128, 3);
    gemm1_qkv<<<g1, blk, SMEM_T>>>(xh, p, FF, FF, FF, DKK);

    // 2) scores (1 sweep) + fused exp -> E fp16 + col psums
    dim3 g2(SS / 128, SS / 128, BB);
    gemm1_scores<<<g2, blk, SMEM_T>>>(q, k, E, psum, 1.0f / 32.0f);

    // 3) rcpd = 1/colsum
    reduce_rcpd<<<BB * SS / 256, 256>>>(psum, rcpd);

    // 4) transpose v -> vT with rcp folded
    dim3 g4(DKK / 32, SS / 32, BB);
    transpose_scale<<<g4, dim3(32, 8)>>>(v, rcpd, vT, SS, DKK);

    // 5) ctx = E @ V' (1 sweep) -> ctx fp16
    dim3 g5(DKK / 128, SS / 128, BB);
    gemm1_tc<<<g5, blk, SMEM_T>>>(E, vT, nullptr, ctx, nullptr,
                                  SS, SS, SS, DKK,
                                  (long long)SS * SS, (long long)DKK * SS,
                                  (long long)SS * DKK);

    // 6) out = ctx @ Wo^T + bo (1 sweep) -> fp32
    dim3 g6(FF / 128, M / 128, 1);
    gemm1_tc<<<g6, blk, SMEM_T>>>(ctx, wo, (float*)d_out, nullptr, bo,
                                  DKK, DKK, DKK, FF, 0, 0, 0);
}

// round 17
// speedup vs baseline: 2.0842x; 1.0027x over previous
#include <cuda_runtime.h>
#include <cuda_fp16.h>
#include <cstdint>

#define BB 4
#define SS 2048
#define FF 1024
#define DKK 1024

// ---------------- scratch (device globals; no allocs allowed) ----------------
__device__ __half  g_x[BB*SS*FF];                          // x fp16
__device__ __half  g_Wq[DKK*FF], g_Wk[DKK*FF], g_Wv[DKK*FF], g_Wo[FF*DKK];
__device__ __half  g_q[BB*SS*DKK];                         // q fp16
__device__ __half  g_k[BB*SS*DKK];                         // k fp16
__device__ __half  g_v[BB*SS*DKK];                         // v fp16
__device__ __half  g_vT[BB*DKK*SS];                        // vT*rcp fp16
__device__ float   g_psum[(size_t)BB*16*SS];
__device__ float   g_rcpd[BB*SS];
__device__ __half  g_E[(size_t)BB*SS*SS];                  // E fp16
__device__ __half  g_ctx[BB*SS*DKK];                       // ctx fp16

// ---------------- PTX helpers ----------------
__device__ __forceinline__ uint32_t smem_to_u32(const void* p) {
    uint32_t a;
    asm("{ .reg .u64 t; cvta.to.shared.u64 t, %1; cvt.u32.u64 %0, t; }" : "=r"(a) : "l"(p));
    return a;
}
__device__ __forceinline__ void cp16(uint32_t dst, const void* src) {
    asm volatile("cp.async.cg.shared.global [%0], [%1], 16;" :: "r"(dst), "l"(src));
}
#define CP_COMMIT() asm volatile("cp.async.commit_group;" ::: "memory")
template <int N> __device__ __forceinline__ void cp_wait() {
    asm volatile("cp.async.wait_group %0;" :: "n"(N) : "memory");
}
__device__ __forceinline__ void ldmx4(uint32_t* r, uint32_t addr) {
    asm volatile("ldmatrix.sync.aligned.m8n8.x4.shared.b16 {%0,%1,%2,%3}, [%4];"
        : "=r"(r[0]), "=r"(r[1]), "=r"(r[2]), "=r"(r[3]) : "r"(addr));
}
__device__ __forceinline__ void mma_f16(float* c, const uint32_t* a, const uint32_t* b) {
    asm volatile(
        "mma.sync.aligned.m16n8k16.row.col.f32.f16.f16.f32 "
        "{%0,%1,%2,%3}, {%4,%5,%6,%7}, {%8,%9}, {%0,%1,%2,%3};"
        : "+f"(c[0]), "+f"(c[1]), "+f"(c[2]), "+f"(c[3])
        : "r"(a[0]), "r"(a[1]), "r"(a[2]), "r"(a[3]), "r"(b[0]), "r"(b[1]));
}

// smem: BK=64 -> rows of 64 elems (128B) @ stride 144B
// 16B-seg bank index (9*i + j) mod 8 covers all 8 -> conflict-free ldmatrix
#define BK     64
#define STRB   144
#define PLANE  (128 * STRB)            // 18432 B
#define BUF    (2 * PLANE)             // A + B planes = 36864 B
#define SMEM_T (2 * BUF)               // 73728 B -> 2 CTAs/SM (147456 <= 228K)

#define GTHREADS 128                   // 4 warps per GEMM CTA

// ---------------------------------------------------------------------------
// Core: NT GEMM via fp16 mma.sync, single operands, 1 sweep.
// 4 warps (2x2 grid), warp tile 64x64, CTA tile 128x128, BK=64, 2-stage.
// Half the chunk boundaries of BK=32 -> half the per-chunk sync/wait overhead.
// EXP=1: writes E=exp(alpha*acc) fp16 + per-tile column psums.
// EXP=0: writes Cf (fp32 + bias) and/or Hh (fp16, + bias).
// ---------------------------------------------------------------------------
template <int EXP>
__device__ __forceinline__ void gemm_core(
    const __half* __restrict__ A, const __half* __restrict__ B,
    float* __restrict__ Cf, __half* __restrict__ Hh,
    const float* __restrict__ bias, float* __restrict__ psum, float alpha,
    int K, int lda, int ldb, int ldc, size_t bm, size_t bn)
{
    extern __shared__ char smem[];
    uint32_t sbase = smem_to_u32(smem);
    int tid = threadIdx.x;
    int lane = tid & 31;
    int warp = tid >> 5;               // 0..3
    int m0w = (warp >> 1) * 64;        // 2x2 warp grid, tile 64(m) x 64(n)
    int n0w = (warp & 1) * 64;

    float acc[4][8][4];
#pragma unroll
    for (int i = 0; i < 4; i++)
#pragma unroll
        for (int j = 0; j < 8; j++)
#pragma unroll
            for (int t = 0; t < 4; t++) acc[i][j][t] = 0.0f;

    int nch = K >> 6;                  // K/64 chunks

    auto prefetch = [&](int c) {
        int k0 = c << 6;
        uint32_t sb = sbase + (uint32_t)(c & 1) * BUF;
#pragma unroll
        for (int it = 0; it < 8; it++) {
            int id = tid + it * GTHREADS;     // 0..1023
            int row = id >> 3;                // 0..127
            int seg = id & 7;                 // 0..7 (16B segments of 128B row)
            uint32_t doff = (uint32_t)(row * STRB + seg * 16);
            cp16(sb + 0 * PLANE + doff, A + (size_t)row * lda + k0 + seg * 8);
            cp16(sb + 1 * PLANE + doff, B + (size_t)row * ldb + k0 + seg * 8);
        }
    };

    int aRow = m0w + (lane & 15);
    uint32_t aColB = (uint32_t)((lane >> 4) * 16);
    int bRow = n0w + ((lane >> 4) << 3) + (lane & 7);
    uint32_t bColB = (uint32_t)(((lane >> 3) & 1) * 16);

    prefetch(0); CP_COMMIT();

    for (int c = 0; c < nch; c++) {
        cp_wait<0>();
        __syncthreads();
        if (c + 1 < nch) { prefetch(c + 1); CP_COMMIT(); }

        uint32_t sb = sbase + (uint32_t)(c & 1) * BUF;
#pragma unroll
        for (int ks = 0; ks < 4; ks++) {
            uint32_t kB = (uint32_t)(ks * 32);
            uint32_t a[4][4];
#pragma unroll
            for (int mf = 0; mf < 4; mf++)
                ldmx4(a[mf], sb + 0 * PLANE +
                      (uint32_t)((aRow + mf * 16) * STRB) + kB + aColB);
            uint32_t b[16];
#pragma unroll
            for (int ng = 0; ng < 4; ng++)
                ldmx4(&b[ng * 4], sb + 1 * PLANE +
                      (uint32_t)((bRow + ng * 16) * STRB) + kB + bColB);
            // 32 independent accumulators -> RAW-free MMA stream
#pragma unroll
            for (int mf = 0; mf < 4; mf++)
#pragma unroll
                for (int nf = 0; nf < 8; nf++)
                    mma_f16(acc[mf][nf], a[mf], &b[nf * 2]);
        }
    }

    int gidr = lane >> 2;
    int tidq = lane & 3;

    if (EXP) {
        float cs[8][2];
#pragma unroll
        for (int nf = 0; nf < 8; nf++) { cs[nf][0] = 0.0f; cs[nf][1] = 0.0f; }
#pragma unroll
        for (int mf = 0; mf < 4; mf++) {
#pragma unroll
            for (int nf = 0; nf < 8; nf++) {
                size_t r0 = bm + m0w + mf * 16 + gidr;
                size_t r1 = r0 + 8;
                size_t col = bn + n0w + nf * 8 + tidq * 2;
                float e00 = __expf(acc[mf][nf][0] * alpha);
                float e01 = __expf(acc[mf][nf][1] * alpha);
                float e10 = __expf(acc[mf][nf][2] * alpha);
                float e11 = __expf(acc[mf][nf][3] * alpha);
                cs[nf][0] += e00 + e10;
                cs[nf][1] += e01 + e11;
                *(__half2*)(Hh + r0 * ldc + col) = __floats2half2_rn(e00, e01);
                *(__half2*)(Hh + r1 * ldc + col) = __floats2half2_rn(e10, e11);
            }
        }
#pragma unroll
        for (int nf = 0; nf < 8; nf++)
#pragma unroll
            for (int t = 0; t < 2; t++) {
                float v = cs[nf][t];
                v += __shfl_xor_sync(0xffffffff, v, 4);
                v += __shfl_xor_sync(0xffffffff, v, 8);
                v += __shfl_xor_sync(0xffffffff, v, 16);
                cs[nf][t] = v;
            }
        float* sred = (float*)smem;   // 256 floats, reuse pipeline smem
        __syncthreads();
        if (gidr == 0) {
#pragma unroll
            for (int nf = 0; nf < 8; nf++) {
                int cl = n0w + nf * 8 + tidq * 2;
                sred[(warp >> 1) * 128 + cl + 0] = cs[nf][0];
                sred[(warp >> 1) * 128 + cl + 1] = cs[nf][1];
            }
        }
        __syncthreads();
        psum[tid] = sred[tid] + sred[128 + tid];
        return;
    }

#pragma unroll
    for (int mf = 0; mf < 4; mf++) {
#pragma unroll
        for (int nf = 0; nf < 8; nf++) {
            size_t r0 = bm + m0w + mf * 16 + gidr;
            size_t r1 = r0 + 8;
            size_t col = bn + n0w + nf * 8 + tidq * 2;
            float b0 = bias ? bias[col] : 0.0f;
            float b1 = bias ? bias[col + 1] : 0.0f;
            float c00 = acc[mf][nf][0] + b0;
            float c01 = acc[mf][nf][1] + b1;
            float c10 = acc[mf][nf][2] + b0;
            float c11 = acc[mf][nf][3] + b1;
            if (Cf) {
                *(float2*)(Cf + r0 * ldc + col) = make_float2(c00, c01);
                *(float2*)(Cf + r1 * ldc + col) = make_float2(c10, c11);
            }
            if (Hh) {
                *(__half2*)(Hh + r0 * ldc + col) = __floats2half2_rn(c00, c01);
                *(__half2*)(Hh + r1 * ldc + col) = __floats2half2_rn(c10, c11);
            }
        }
    }
}

// Generic batched single-fp16 NT GEMM
__global__ __launch_bounds__(GTHREADS, 2) void gemm1_tc(
    const __half* __restrict__ A, const __half* __restrict__ B,
    float* __restrict__ Cf, __half* __restrict__ Hh,
    const float* __restrict__ bias,
    int K, int lda, int ldb, int ldc,
    long long sA, long long sB, long long sC)
{
    int bz = blockIdx.z;
    size_t bm = (size_t)blockIdx.y * 128;
    size_t bn = (size_t)blockIdx.x * 128;
    gemm_core<0>(A + (size_t)bz * sA + bm * lda,
                 B + (size_t)bz * sB + bn * ldb,
                 Cf ? Cf + (size_t)bz * sC : nullptr,
                 Hh ? Hh + (size_t)bz * sC : nullptr,
                 bias, nullptr, 0.0f, K, lda, ldb, ldc, bm, bn);
}

// Scores: fused exp epilogue
__global__ __launch_bounds__(GTHREADS, 2) void gemm1_scores(
    const __half* __restrict__ Q, const __half* __restrict__ Ks,
    __half* __restrict__ E, float* __restrict__ psum_all, float alpha)
{
    int bz = blockIdx.z;
    size_t bm = (size_t)blockIdx.y * 128;
    size_t bn = (size_t)blockIdx.x * 128;
    float* ps = psum_all + ((size_t)bz * gridDim.y + blockIdx.y) * SS + bn;
    gemm_core<1>(Q + (size_t)bz * SS * DKK + bm * DKK,
                 Ks + (size_t)bz * SS * DKK + bn * DKK,
                 nullptr, E + (size_t)bz * SS * SS,
                 nullptr, ps, alpha, DKK, DKK, DKK, SS, bm, bn);
}

// Fused QKV: z selects weight/bias/output
struct QKVP {
    const __half* W[3];
    const float* bias[3];
    __half* O[3];
};
__global__ __launch_bounds__(GTHREADS, 2) void gemm1_qkv(
    const __half* __restrict__ X, QKVP p, int K, int lda, int ldb, int ldc)
{
    int z = blockIdx.z;
    size_t bm = (size_t)blockIdx.y * 128;
    size_t bn = (size_t)blockIdx.x * 128;
    gemm_core<0>(X + bm * lda, p.W[z] + bn * ldb,
                 nullptr, p.O[z], p.bias[z], nullptr, 0.0f,
                 K, lda, ldb, ldc, bm, bn);
}

// ---------------------------------------------------------------------------
// fp32 -> fp16 conversions: x + 4 weights, one launch
// ---------------------------------------------------------------------------
struct ConvP {
    const float* in[5];
    __half* out[5];
    long long n4[5];
};
__global__ __launch_bounds__(256) void conv_h5(ConvP p)
{
    int w = blockIdx.y;
    long long i = (long long)blockIdx.x * blockDim.x + threadIdx.x;
    if (i >= p.n4[w]) return;
    float4 v = ((const float4*)p.in[w])[i];
    ((__half2*)p.out[w])[2 * i] = __floats2half2_rn(v.x, v.y);
    ((__half2*)p.out[w])[2 * i + 1] = __floats2half2_rn(v.z, v.w);
}

__global__ __launch_bounds__(256) void reduce_rcpd(
    const float* __restrict__ psum, float* __restrict__ rcpd)
{
    int i = blockIdx.x * blockDim.x + threadIdx.x;
    int b = i >> 11;
    int col = i & (SS - 1);
    const float* p = psum + (size_t)b * 16 * SS + col;
    float s = 0.0f;
#pragma unroll
    for (int t = 0; t < 16; t++) s += p[(size_t)t * SS];
    rcpd[i] = 1.0f / s;
}

// transpose + scale: vT[d][k] = v[k][d] * rcp[k], fp16
__global__ __launch_bounds__(256) void transpose_scale(
    const __half* __restrict__ iv, const float* __restrict__ rcpd,
    __half* __restrict__ oT, int rows, int cols)
{
    __shared__ __half t0[32][33];
    int z = blockIdx.z;
    size_t ioff = (size_t)z * rows * cols;
    int c0 = blockIdx.x * 32, r0 = blockIdx.y * 32;
    int tx = threadIdx.x, ty = threadIdx.y;

#pragma unroll
    for (int j = 0; j < 32; j += 8) {
        int r = r0 + ty + j;
        float rcp = rcpd[(size_t)z * rows + r];
        size_t idx = ioff + (size_t)r * cols + c0 + tx;
        t0[ty + j][tx] = __float2half(__half2float(iv[idx]) * rcp);
    }
    __syncthreads();
#pragma unroll
    for (int j = 0; j < 32; j += 8) {
        size_t odx = ioff + (size_t)(c0 + ty + j) * rows + r0 + tx;
        oT[odx] = t0[tx][ty + j];
    }
}

// ---------------------------------------------------------------------------
extern "C" void kernel_launch(void* const* d_in, const int* in_sizes, int n_in,
                              void* d_out, int out_size)
{
    const float* x  = (const float*)d_in[0];
    const float* Wq = (const float*)d_in[1];
    const float* bq = (const float*)d_in[2];
    const float* Wk = (const float*)d_in[3];
    const float* bk = (const float*)d_in[4];
    const float* Wv = (const float*)d_in[5];
    const float* bv = (const float*)d_in[6];
    const float* Wo = (const float*)d_in[7];
    const float* bo = (const float*)d_in[8];

    __half *xh, *wq, *wk, *wv, *wo, *q, *k, *v, *vT, *E, *ctx;
    float *psum, *rcpd;
    cudaGetSymbolAddress((void**)&xh, g_x);
    cudaGetSymbolAddress((void**)&wq, g_Wq);  cudaGetSymbolAddress((void**)&wk, g_Wk);
    cudaGetSymbolAddress((void**)&wv, g_Wv);  cudaGetSymbolAddress((void**)&wo, g_Wo);
    cudaGetSymbolAddress((void**)&q, g_q);    cudaGetSymbolAddress((void**)&k, g_k);
    cudaGetSymbolAddress((void**)&v, g_v);    cudaGetSymbolAddress((void**)&vT, g_vT);
    cudaGetSymbolAddress((void**)&E, g_E);    cudaGetSymbolAddress((void**)&ctx, g_ctx);
    cudaGetSymbolAddress((void**)&psum, g_psum);
    cudaGetSymbolAddress((void**)&rcpd, g_rcpd);

    cudaFuncSetAttribute(gemm1_tc,     cudaFuncAttributeMaxDynamicSharedMemorySize, SMEM_T);
    cudaFuncSetAttribute(gemm1_qkv,    cudaFuncAttributeMaxDynamicSharedMemorySize, SMEM_T);
    cudaFuncSetAttribute(gemm1_scores, cudaFuncAttributeMaxDynamicSharedMemorySize, SMEM_T);

    const int M = BB * SS;  // 8192

    // 0) conversions: x + 4 weights, one launch
    ConvP cp;
    cp.in[0] = x;  cp.out[0] = xh; cp.n4[0] = (long long)M * FF / 4;
    cp.in[1] = Wq; cp.out[1] = wq; cp.n4[1] = (long long)DKK * FF / 4;
    cp.in[2] = Wk; cp.out[2] = wk; cp.n4[2] = (long long)DKK * FF / 4;
    cp.in[3] = Wv; cp.out[3] = wv; cp.n4[3] = (long long)DKK * FF / 4;
    cp.in[4] = Wo; cp.out[4] = wo; cp.n4[4] = (long long)FF * DKK / 4;
    conv_h5<<<dim3((M * FF / 4 + 255) / 256, 5), 256>>>(cp);

    dim3 blk(GTHREADS);

    // 1) fused QKV (1 sweep) -> q,k,v (+bias)
    QKVP p;
    p.W[0] = wq; p.bias[0] = bq; p.O[0] = q;
    p.W[1] = wk; p.bias[1] = bk; p.O[1] = k;
    p.W[2] = wv; p.bias[2] = bv; p.O[2] = v;
    dim3 g1(DKK / 128, M / 128, 3);
    gemm1_qkv<<<g1, blk, SMEM_T>>>(xh, p, FF, FF, FF, DKK);

    // 2) scores (1 sweep) + fused exp -> E fp16 + col psums
    dim3 g2(SS / 128, SS / 128, BB);
    gemm1_scores<<<g2, blk, SMEM_T>>>(q, k, E, psum, 1.0f / 32.0f);

    // 3) rcpd = 1/colsum
    reduce_rcpd<<<BB * SS / 256, 256>>>(psum, rcpd);

    // 4) transpose v -> vT with rcp folded
    dim3 g4(DKK / 32, SS / 32, BB);
    transpose_scale<<<g4, dim3(32, 8)>>>(v, rcpd, vT, SS, DKK);

    // 5) ctx = E @ V' (1 sweep) -> ctx fp16
    dim3 g5(DKK / 128, SS / 128, BB);
    gemm1_tc<<<g5, blk, SMEM_T>>>(E, vT, nullptr, ctx, nullptr,
                                  SS, SS, SS, DKK,
                                  (long long)SS * SS, (long long)DKK * SS,
                                  (long long)SS * DKK);

    // 6) out = ctx @ Wo^T + bo (1 sweep) -> fp32
    dim3 g6(FF / 128, M / 128, 1);
    gemm1_tc<<<g6, blk, SMEM_T>>>(ctx, wo, (float*)d_out, nullptr, bo,
                                  DKK, DKK, DKK, FF, 0, 0, 0);
}